// round 12
// baseline (speedup 1.0000x reference)
#include <cuda_runtime.h>
#include <cuda_fp16.h>
#include <cstdint>

#define NNODES 20000
#define NEDGES 320000
#define NEPLUS 340000   // edges + self loops
#define NGRAPH 256
#define VOCAB  128
#define NWH    294912   // fp16 weights: W2(65536) lw2(65536) W3(131072) lw3(32768)
#define MBLK   157      // ceil(20000/128)
#define GATBLK 2500     // ceil(20000/8) warps-per-node blocks

// ---------------- scratch (device globals; no runtime alloc allowed) ----------------
__device__ float  g_feat [2][NNODES * 128];  // layer-3 output (fp32, pooled)
__device__ __half g_feath[2][NNODES * 256];  // concat-layer outputs (GEMM inputs)
__device__ __half g_xh   [2][NNODES * 512];  // fp16 message features
__device__ float  g_lin  [2][NNODES * 256];
__device__ float  g_asb  [3][2][NNODES * 4]; // per-layer src scores (l0 store, l1/l2 atomic)
__device__ float  g_adb  [3][2][NNODES * 4];
__device__ float  g_exp  [2][NEPLUS * 4];    // cached per-edge exp
__device__ int    g_off  [2][NNODES + 1];
__device__ int    g_cur  [2][NNODES];
__device__ int    g_srcs [2][NEPLUS];
__device__ int    g_gcnt [2][NGRAPH];
__device__ int    g_bsum [2][128];
__device__ float  g_tab  [VOCAB * 512];
__device__ float  g_tatt [VOCAB * 8];
__device__ __half g_wh   [NWH];

__device__ __forceinline__ float lrelu(float x) { return x > 0.f ? x : 0.2f * x; }

__device__ __forceinline__ uint32_t sptr(const void* p) {
    return (uint32_t)__cvta_generic_to_shared(p);
}
#define CPA(dst, src, sz) \
    asm volatile("cp.async.cg.shared.global [%0], [%1], 16, %2;" :: "r"(dst), "l"(src), "r"(sz))
#define CP_COMMIT() asm volatile("cp.async.commit_group;" ::: "memory")
#define CP_WAIT1()  asm volatile("cp.async.wait_group 1;" ::: "memory")
#define CP_WAIT0()  asm volatile("cp.async.wait_group 0;" ::: "memory")

// ---------------- init: weight conversion + zero buffers + CSR counts ----------------
__global__ void k_init(const float* __restrict__ W2, const float* __restrict__ lw2,
                       const float* __restrict__ W3, const float* __restrict__ lw3,
                       float* out) {
    int i = blockIdx.x * blockDim.x + threadIdx.x;
    if (i < NWH) {
        float v;
        if (i < 65536)       v = W2[i];
        else if (i < 131072) v = lw2[i - 65536];
        else if (i < 262144) v = W3[i - 131072];
        else                 v = lw3[i - 262144];
        g_wh[i] = __float2half_rn(v);
    }
    if (i < 2 * NNODES) g_cur[i / NNODES][i % NNODES] = 1;
    if (i < 2 * NGRAPH * 128) out[i] = 0.f;
    if (i < 2 * NGRAPH) g_gcnt[i >> 8][i & 255] = 0;
    // zero score layers 1 and 2 (atomically accumulated by gemm epilogues)
    if (i < 2 * 2 * NNODES * 4) {
        int l = 1 + i / (2 * NNODES * 4);
        int r = i % (2 * NNODES * 4);
        g_asb[l][r / (NNODES * 4)][r % (NNODES * 4)] = 0.f;
        g_adb[l][r / (NNODES * 4)][r % (NNODES * 4)] = 0.f;
    }
}

// ---------------- layer-1 precompute: tables over the 128-entry vocab ----------------
__global__ void k_pre(const float* __restrict__ emb, const float* __restrict__ W1,
                      const float* __restrict__ lw1, const float* __restrict__ as1,
                      const float* __restrict__ ad1) {
    __shared__ float er[128];
    __shared__ float sAs[4], sAd[4];
    int v = blockIdx.x, t = threadIdx.x;  // 256 threads
    if (t < 128) er[t] = emb[v * 128 + t];
    if (t < 4) { sAs[t] = 0.f; sAd[t] = 0.f; }
    __syncthreads();
    float acc0 = 0.f, acc1 = 0.f;
    for (int k = 0; k < 128; k++) {
        float e = er[k];
        acc0 += e * W1[k * 256 + t];
        acc1 += e * lw1[k * 256 + t];
    }
    g_tab[v * 512 + t] = acc0;
    g_tab[v * 512 + 256 + t] = acc1;
    int h = t >> 6, c = t & 63;
    atomicAdd(&sAs[h], acc0 * as1[h * 64 + c]);
    atomicAdd(&sAd[h], acc0 * ad1[h * 64 + c]);
    __syncthreads();
    if (t < 4) { g_tatt[v * 8 + t] = sAs[t]; g_tatt[v * 8 + 4 + t] = sAd[t]; }
}

// ---------------- CSR build ----------------
__global__ void k_hist(const int* __restrict__ el, const int* __restrict__ er) {
    int side = blockIdx.z;
    const int* edge = side ? er : el;
    int e = blockIdx.x * blockDim.x + threadIdx.x;
    if (e < NEDGES) atomicAdd(&g_cur[side][edge[NEDGES + e]], 1);
}

__global__ void k_scan_a() {
    int side = blockIdx.z;
    __shared__ int sh[256];
    int t = threadIdx.x, i = blockIdx.x * 256 + t;
    int v = (i < NNODES) ? g_cur[side][i] : 0;
    sh[t] = v;
    __syncthreads();
    for (int o = 1; o < 256; o <<= 1) {
        int x = (t >= o) ? sh[t - o] : 0;
        __syncthreads();
        sh[t] += x;
        __syncthreads();
    }
    if (i < NNODES) g_off[side][i] = sh[t] - v;
    if (t == 255) g_bsum[side][blockIdx.x] = sh[255];
}
__global__ void k_scan_b() {
    int side = blockIdx.x, lane = threadIdx.x;
    int v[3]; int s = 0;
#pragma unroll
    for (int j = 0; j < 3; j++) {
        int b = lane * 3 + j;
        v[j] = (b < 79) ? g_bsum[side][b] : 0;
        s += v[j];
    }
    int ps = s;
    for (int o = 1; o < 32; o <<= 1) {
        int u = __shfl_up_sync(0xffffffffu, ps, o);
        if (lane >= o) ps += u;
    }
    int run = ps - s;
#pragma unroll
    for (int j = 0; j < 3; j++) {
        int b = lane * 3 + j;
        if (b < 79) g_bsum[side][b] = run;
        run += v[j];
    }
}
__global__ void k_scan_c() {
    int side = blockIdx.z;
    int i = blockIdx.x * 256 + threadIdx.x;
    if (i < NNODES) {
        int o = g_off[side][i] + g_bsum[side][i >> 8];
        g_off[side][i] = o;
        g_cur[side][i] = o;
    }
    if (i == 0) g_off[side][NNODES] = NEPLUS;
}

__global__ void k_scatter(const int* __restrict__ el, const int* __restrict__ er) {
    int side = blockIdx.z;
    const int* edge = side ? er : el;
    int e = blockIdx.x * blockDim.x + threadIdx.x;
    if (e < NEPLUS) {
        int s, d;
        if (e < NEDGES) { s = edge[e]; d = edge[NEDGES + e]; }
        else            { s = d = e - NEDGES; }
        int p = atomicAdd(&g_cur[side][d], 1);
        g_srcs[side][p] = s;
    }
}

// ---------------- layer-1 "GEMM" via table gather ----------------
__global__ void k_l1gather(const int* __restrict__ xl, const int* __restrict__ xr) {
    int side = blockIdx.z;
    const int* xi = side ? xr : xl;
    int idx = blockIdx.x * blockDim.x + threadIdx.x;
    if (idx >= NNODES * 128) return;
    int n = idx >> 7, q = idx & 127;
    int v = xi[n];
    float4 val = *(const float4*)(g_tab + v * 512 + q * 4);
    if (q < 64) {
        __half2 h0 = __floats2half2_rn(val.x, val.y);
        __half2 h1 = __floats2half2_rn(val.z, val.w);
        uint2 u = make_uint2(*(uint32_t*)&h0, *(uint32_t*)&h1);
        *(uint2*)(&g_xh[side][n * 256 + q * 4]) = u;
    } else {
        *(float4*)(&g_lin[side][n * 256 + (q - 64) * 4]) = val;
    }
    if (q == 0) {
        *(float4*)(&g_asb[0][side][n * 4]) = *(const float4*)(g_tatt + v * 8);
        *(float4*)(&g_adb[0][side][n * 4]) = *(const float4*)(g_tatt + v * 8 + 4);
    }
}

// ---------------- fp16 GEMM device function with fused attention-score epilogue -----
__device__ __forceinline__ void mma_f16(float* c, const unsigned* a, const unsigned* b) {
    asm volatile(
        "mma.sync.aligned.m16n8k16.row.col.f32.f16.f16.f32 "
        "{%0,%1,%2,%3},{%4,%5,%6,%7},{%8,%9},{%0,%1,%2,%3};"
        : "+f"(c[0]), "+f"(c[1]), "+f"(c[2]), "+f"(c[3])
        : "r"(a[0]), "r"(a[1]), "r"(a[2]), "r"(a[3]),
          "r"(b[0]), "r"(b[1]));
}

#define AS_STRIDE 40
#define BS_STRIDE 136
#define GEMM_SMEM ((2 * 128 * AS_STRIDE + 2 * 32 * BS_STRIDE) * 2)

__device__ void dev_gemm(
    int bx, int by, int side, int layer,
    const __half* __restrict__ B1, int N1,
    const __half* __restrict__ B2, int N2,
    int K, const float* __restrict__ atts, const float* __restrict__ attd, int C) {
    extern __shared__ __half smh[];
    __half (*As)[128][AS_STRIDE] = (__half (*)[128][AS_STRIDE])smh;
    __half (*Bs)[32][BS_STRIDE] = (__half (*)[32][BS_STRIDE])(smh + 2 * 128 * AS_STRIDE);

    const int M = NNODES;
    const __half* A = g_feath[side];
    int t1 = N1 >> 7;
    bool ishalf = (bx < t1);
    const __half* B; int N, n0;
    __half* Ch = g_xh[side];
    float* Cf = g_lin[side];
    if (ishalf) { B = B1; N = N1; n0 = bx << 7; }
    else        { B = B2; N = N2; n0 = (bx - t1) << 7; }

    int tid = threadIdx.x;
    int warp = tid >> 5, lane = tid & 31;
    int m0 = by * 128;
    int wm = (warp >> 2) * 64;
    int wn = (warp & 3) * 32;
    int gid = lane >> 2, tig = lane & 3;

    float c[4][4][4];
#pragma unroll
    for (int i = 0; i < 4; i++)
#pragma unroll
        for (int j = 0; j < 4; j++)
#pragma unroll
            for (int r = 0; r < 4; r++) c[i][j][r] = 0.f;

    auto load_tile = [&](int s, int kk) {
#pragma unroll
        for (int i = 0; i < 2; i++) {
            int cid = tid + 256 * i;
            int row = cid >> 2, coff = (cid & 3) * 8;
            const __half* asrc = A + (size_t)(m0 + row) * K + kk + coff;
            int sz = (m0 + row < M) ? 16 : 0;
            if (!sz) asrc = A;
            CPA(sptr(&As[s][row][coff]), asrc, sz);
            int krow = cid >> 4, noff = (cid & 15) * 8;
            const __half* bsrc = B + (size_t)(kk + krow) * N + n0 + noff;
            CPA(sptr(&Bs[s][krow][noff]), bsrc, 16);
        }
        CP_COMMIT();
    };

    auto compute = [&](int s) {
#pragma unroll
        for (int ks = 0; ks < 2; ks++) {
            unsigned a[4][4], b[4][2];
#pragma unroll
            for (int mi = 0; mi < 4; mi++) {
                uint32_t addr = sptr(&As[s][wm + mi * 16 + (lane & 15)][ks * 16 + (lane >> 4) * 8]);
                asm volatile("ldmatrix.sync.aligned.m8n8.x4.shared.b16 {%0,%1,%2,%3}, [%4];"
                             : "=r"(a[mi][0]), "=r"(a[mi][1]), "=r"(a[mi][2]), "=r"(a[mi][3])
                             : "r"(addr));
            }
#pragma unroll
            for (int ni = 0; ni < 4; ni++) {
                uint32_t addr = sptr(&Bs[s][ks * 16 + (lane & 15)][wn + ni * 8]);
                asm volatile("ldmatrix.sync.aligned.m8n8.x2.trans.shared.b16 {%0,%1}, [%2];"
                             : "=r"(b[ni][0]), "=r"(b[ni][1])
                             : "r"(addr));
            }
#pragma unroll
            for (int mi = 0; mi < 4; mi++)
#pragma unroll
                for (int ni = 0; ni < 4; ni++) mma_f16(c[mi][ni], a[mi], b[ni]);
        }
    };

    int KT = K >> 5;
    load_tile(0, 0);
    for (int kt = 0; kt < KT; kt++) {
        if (kt + 1 < KT) {
            load_tile((kt + 1) & 1, (kt + 1) << 5);
            CP_WAIT1();
        } else {
            CP_WAIT0();
        }
        __syncthreads();
        compute(kt & 1);
        __syncthreads();
    }
#pragma unroll
    for (int mi = 0; mi < 4; mi++) {
#pragma unroll
        for (int ni = 0; ni < 4; ni++) {
            int r0 = m0 + wm + mi * 16 + gid;
            int cc = n0 + wn + ni * 8 + tig * 2;
            if (ishalf) {
                if (r0 < M)
                    *(__half2*)(Ch + (size_t)r0 * N + cc) =
                        __floats2half2_rn(c[mi][ni][0], c[mi][ni][1]);
                if (r0 + 8 < M)
                    *(__half2*)(Ch + (size_t)(r0 + 8) * N + cc) =
                        __floats2half2_rn(c[mi][ni][2], c[mi][ni][3]);
            } else {
                if (r0 < M)
                    *(float2*)(Cf + (size_t)r0 * N + cc) = make_float2(c[mi][ni][0], c[mi][ni][1]);
                if (r0 + 8 < M)
                    *(float2*)(Cf + (size_t)(r0 + 8) * N + cc) = make_float2(c[mi][ni][2], c[mi][ni][3]);
            }
        }
    }
    // ---- fused attention-score epilogue (xh blocks only) ----
    if (ishalf) {
        int h = (n0 + wn) / C;   // warp's 32 cols lie within one head
        float av0[4], av1[4], bv0[4], bv1[4];
#pragma unroll
        for (int ni = 0; ni < 4; ni++) {
            int cc = n0 + wn + ni * 8 + tig * 2;
            av0[ni] = atts[cc]; av1[ni] = atts[cc + 1];
            bv0[ni] = attd[cc]; bv1[ni] = attd[cc + 1];
        }
        float* asb = g_asb[layer][side];
        float* adb = g_adb[layer][side];
#pragma unroll
        for (int mi = 0; mi < 4; mi++) {
            float s0 = 0.f, s1 = 0.f, d0 = 0.f, d1 = 0.f;
#pragma unroll
            for (int ni = 0; ni < 4; ni++) {
                s0 += c[mi][ni][0] * av0[ni] + c[mi][ni][1] * av1[ni];
                s1 += c[mi][ni][2] * av0[ni] + c[mi][ni][3] * av1[ni];
                d0 += c[mi][ni][0] * bv0[ni] + c[mi][ni][1] * bv1[ni];
                d1 += c[mi][ni][2] * bv0[ni] + c[mi][ni][3] * bv1[ni];
            }
#pragma unroll
            for (int o = 1; o <= 2; o <<= 1) {
                s0 += __shfl_xor_sync(0xffffffffu, s0, o);
                s1 += __shfl_xor_sync(0xffffffffu, s1, o);
                d0 += __shfl_xor_sync(0xffffffffu, d0, o);
                d1 += __shfl_xor_sync(0xffffffffu, d1, o);
            }
            if (tig == 0) {
                int r0 = m0 + wm + mi * 16 + gid;
                if (r0 < M) {
                    atomicAdd(&asb[r0 * 4 + h], s0);
                    atomicAdd(&adb[r0 * 4 + h], d0);
                }
                if (r0 + 8 < M) {
                    atomicAdd(&asb[(r0 + 8) * 4 + h], s1);
                    atomicAdd(&adb[(r0 + 8) * 4 + h], d1);
                }
            }
        }
    }
}

// ---------------- GAT device functions (R10 structure) ----------------
__device__ void dev_gat_concat(int side, int layer, int i, int lane,
                               const float* __restrict__ bias,
                               const float* __restrict__ lbias, int relu_flag) {
    int beg = g_off[side][i], end = g_off[side][i + 1];
    const float* asbuf = g_asb[layer][side];
    float4 ad = *(const float4*)(&g_adb[layer][side][(size_t)i * 4]);
    float z0 = 0.f, z1 = 0.f, z2 = 0.f, z3 = 0.f;
    for (int e = beg + lane; e < end; e += 32) {
        int s = g_srcs[side][e];
        float4 as = *(const float4*)(&asbuf[(size_t)s * 4]);
        float e0 = __expf(fminf(lrelu(as.x + ad.x), 80.f));
        float e1 = __expf(fminf(lrelu(as.y + ad.y), 80.f));
        float e2 = __expf(fminf(lrelu(as.z + ad.z), 80.f));
        float e3 = __expf(fminf(lrelu(as.w + ad.w), 80.f));
        *(float4*)(&g_exp[side][(size_t)e * 4]) = make_float4(e0, e1, e2, e3);
        z0 += e0; z1 += e1; z2 += e2; z3 += e3;
    }
    for (int o = 16; o; o >>= 1) {
        z0 += __shfl_xor_sync(0xffffffffu, z0, o);
        z1 += __shfl_xor_sync(0xffffffffu, z1, o);
        z2 += __shfl_xor_sync(0xffffffffu, z2, o);
        z3 += __shfl_xor_sync(0xffffffffu, z3, o);
    }
    float i0 = 1.f / (z0 + 1e-16f), i1 = 1.f / (z1 + 1e-16f);
    float i2 = 1.f / (z2 + 1e-16f), i3 = 1.f / (z3 + 1e-16f);
    int h = lane >> 3;
    float myinv = (h == 0) ? i0 : (h == 1) ? i1 : (h == 2) ? i2 : i3;
    int col = lane * 8;
    float a0 = 0.f, a1 = 0.f, a2 = 0.f, a3 = 0.f, a4 = 0.f, a5 = 0.f, a6 = 0.f, a7 = 0.f;
    for (int e = beg; e < end; e++) {
        int s = g_srcs[side][e];
        float w = g_exp[side][(size_t)e * 4 + h] * myinv;
        uint4 u = *(const uint4*)(g_xh[side] + (size_t)s * 256 + col);
        __half2* hp = (__half2*)&u;
        float2 f0 = __half22float2(hp[0]);
        float2 f1 = __half22float2(hp[1]);
        float2 f2 = __half22float2(hp[2]);
        float2 f3 = __half22float2(hp[3]);
        a0 += w * f0.x; a1 += w * f0.y; a2 += w * f1.x; a3 += w * f1.y;
        a4 += w * f2.x; a5 += w * f2.y; a6 += w * f3.x; a7 += w * f3.y;
    }
    float4 lr0 = *(const float4*)(g_lin[side] + (size_t)i * 256 + col);
    float4 lr1 = *(const float4*)(g_lin[side] + (size_t)i * 256 + col + 4);
    float4 b0 = *(const float4*)(bias + col);
    float4 b1 = *(const float4*)(bias + col + 4);
    float4 lb0 = *(const float4*)(lbias + col);
    float4 lb1 = *(const float4*)(lbias + col + 4);
    float o0x = a0 + b0.x + lr0.x + lb0.x, o0y = a1 + b0.y + lr0.y + lb0.y;
    float o0z = a2 + b0.z + lr0.z + lb0.z, o0w = a3 + b0.w + lr0.w + lb0.w;
    float o1x = a4 + b1.x + lr1.x + lb1.x, o1y = a5 + b1.y + lr1.y + lb1.y;
    float o1z = a6 + b1.z + lr1.z + lb1.z, o1w = a7 + b1.w + lr1.w + lb1.w;
    if (relu_flag) {
        o0x = fmaxf(o0x, 0.f); o0y = fmaxf(o0y, 0.f);
        o0z = fmaxf(o0z, 0.f); o0w = fmaxf(o0w, 0.f);
        o1x = fmaxf(o1x, 0.f); o1y = fmaxf(o1y, 0.f);
        o1z = fmaxf(o1z, 0.f); o1w = fmaxf(o1w, 0.f);
    }
    __half2 h0 = __floats2half2_rn(o0x, o0y);
    __half2 h1 = __floats2half2_rn(o0z, o0w);
    __half2 h2 = __floats2half2_rn(o1x, o1y);
    __half2 h3 = __floats2half2_rn(o1z, o1w);
    uint4 uo = make_uint4(*(uint32_t*)&h0, *(uint32_t*)&h1, *(uint32_t*)&h2, *(uint32_t*)&h3);
    *(uint4*)(&g_feath[side][(size_t)i * 256 + col]) = uo;
}

__device__ void dev_gat_mean(int side, int layer, int i, int lane,
                             const float* __restrict__ bias,
                             const float* __restrict__ lbias) {
    int beg = g_off[side][i], end = g_off[side][i + 1];
    const float* asbuf = g_asb[layer][side];
    float4 ad = *(const float4*)(&g_adb[layer][side][(size_t)i * 4]);
    float z0 = 0.f, z1 = 0.f, z2 = 0.f, z3 = 0.f;
    for (int e = beg + lane; e < end; e += 32) {
        int s = g_srcs[side][e];
        float4 as = *(const float4*)(&asbuf[(size_t)s * 4]);
        float e0 = __expf(fminf(lrelu(as.x + ad.x), 80.f));
        float e1 = __expf(fminf(lrelu(as.y + ad.y), 80.f));
        float e2 = __expf(fminf(lrelu(as.z + ad.z), 80.f));
        float e3 = __expf(fminf(lrelu(as.w + ad.w), 80.f));
        *(float4*)(&g_exp[side][(size_t)e * 4]) = make_float4(e0, e1, e2, e3);
        z0 += e0; z1 += e1; z2 += e2; z3 += e3;
    }
    for (int o = 16; o; o >>= 1) {
        z0 += __shfl_xor_sync(0xffffffffu, z0, o);
        z1 += __shfl_xor_sync(0xffffffffu, z1, o);
        z2 += __shfl_xor_sync(0xffffffffu, z2, o);
        z3 += __shfl_xor_sync(0xffffffffu, z3, o);
    }
    float i0 = 1.f / (z0 + 1e-16f), i1 = 1.f / (z1 + 1e-16f);
    float i2 = 1.f / (z2 + 1e-16f), i3 = 1.f / (z3 + 1e-16f);
    int h = lane >> 3;
    float myinv = (h == 0) ? i0 : (h == 1) ? i1 : (h == 2) ? i2 : i3;
    int col = lane * 16;
    float acc[16];
#pragma unroll
    for (int j = 0; j < 16; j++) acc[j] = 0.f;
    for (int e = beg; e < end; e++) {
        int s = g_srcs[side][e];
        float w = g_exp[side][(size_t)e * 4 + h] * myinv;
        const uint4* xr = (const uint4*)(g_xh[side] + (size_t)s * 512 + col);
        uint4 u0 = xr[0], u1 = xr[1];
        __half2* hp0 = (__half2*)&u0;
        __half2* hp1 = (__half2*)&u1;
#pragma unroll
        for (int j = 0; j < 4; j++) {
            float2 f = __half22float2(hp0[j]);
            acc[j * 2] += w * f.x; acc[j * 2 + 1] += w * f.y;
        }
#pragma unroll
        for (int j = 0; j < 4; j++) {
            float2 f = __half22float2(hp1[j]);
            acc[8 + j * 2] += w * f.x; acc[8 + j * 2 + 1] += w * f.y;
        }
    }
#pragma unroll
    for (int mask = 8; mask <= 16; mask <<= 1)
#pragma unroll
        for (int j = 0; j < 16; j++)
            acc[j] += __shfl_xor_sync(0xffffffffu, acc[j], mask);
    if (lane < 8) {
        int c0 = lane * 16;
#pragma unroll
        for (int j = 0; j < 4; j++) {
            int c = c0 + j * 4;
            float4 lr = *(const float4*)(g_lin[side] + (size_t)i * 128 + c);
            float4 bb = *(const float4*)(bias + c);
            float4 lb = *(const float4*)(lbias + c);
            float4 o;
            o.x = 0.25f * acc[j * 4 + 0] + bb.x + lr.x + lb.x;
            o.y = 0.25f * acc[j * 4 + 1] + bb.y + lr.y + lb.y;
            o.z = 0.25f * acc[j * 4 + 2] + bb.z + lr.z + lb.z;
            o.w = 0.25f * acc[j * 4 + 3] + bb.w + lr.w + lb.w;
            *(float4*)(g_feat[side] + (size_t)i * 128 + c) = o;
        }
    }
}

// ---------------- standalone GAT kernels ----------------
__global__ __launch_bounds__(256) void k_gat_concat(
    int side, int layer, const float* __restrict__ bias,
    const float* __restrict__ lbias, int relu_flag) {
    int i = blockIdx.x * 8 + (threadIdx.x >> 5);
    if (i < NNODES) dev_gat_concat(side, layer, i, threadIdx.x & 31, bias, lbias, relu_flag);
}
__global__ __launch_bounds__(256) void k_gat_mean(
    int side, const float* __restrict__ bias, const float* __restrict__ lbias) {
    int i = blockIdx.x * 8 + (threadIdx.x >> 5);
    if (i < NNODES) dev_gat_mean(side, 2, i, threadIdx.x & 31, bias, lbias);
}

// ---------------- FUSED: gemm(side A, layer) + gat(side B) in one launch ------------
__global__ __launch_bounds__(256) void k_fused(
    int gemm_side, int layer,
    const __half* __restrict__ B1, int N1,
    const __half* __restrict__ B2, int N2, int K,
    const float* __restrict__ atts, const float* __restrict__ attd, int C,
    int GX, int GB,
    int gat_side, int gat_layer, int gat_mode,
    const float* __restrict__ gbias, const float* __restrict__ glbias, int grelu) {
    if ((int)blockIdx.x < GB) {
        dev_gemm(blockIdx.x % GX, blockIdx.x / GX, gemm_side, layer, B1, N1, B2, N2, K,
                 atts, attd, C);
    } else {
        int gb = blockIdx.x - GB;
        int i = gb * 8 + (threadIdx.x >> 5);
        if (i < NNODES) {
            if (gat_mode == 0)
                dev_gat_concat(gat_side, gat_layer, i, threadIdx.x & 31, gbias, glbias, grelu);
            else
                dev_gat_mean(gat_side, gat_layer, i, threadIdx.x & 31, gbias, glbias);
        }
    }
}

// ---------------- global mean pool ----------------
#define POOL_NB 64
__global__ void k_pool_sum(const int* __restrict__ bl, const int* __restrict__ br, float* out) {
    int side = blockIdx.z;
    const int* batch = side ? br : bl;
    float* po = out + side * NGRAPH * 128;
    int n0 = blockIdx.x * POOL_NB;
    int c = threadIdx.x & 127;
    int r = threadIdx.x >> 7;
    float acc = 0.f;
    int cur = -1, cnt = 0;
    for (int j = r; j < POOL_NB; j += 2) {
        int n = n0 + j;
        if (n >= NNODES) break;
        int b = batch[n];
        if (b != cur) {
            if (cur >= 0) {
                atomicAdd(&po[cur * 128 + c], acc);
                if (c == 0) atomicAdd(&g_gcnt[side][cur], cnt);
            }
            acc = 0.f; cnt = 0; cur = b;
        }
        acc += g_feat[side][(size_t)n * 128 + c];
        cnt++;
    }
    if (cur >= 0) {
        atomicAdd(&po[cur * 128 + c], acc);
        if (c == 0) atomicAdd(&g_gcnt[side][cur], cnt);
    }
}
__global__ void k_pool_div(float* out) {
    int i = blockIdx.x * blockDim.x + threadIdx.x;
    if (i < 2 * NGRAPH * 128) {
        int side = i >> 15;
        float cnt = (float)g_gcnt[side][(i >> 7) & 255];
        out[i] /= fmaxf(cnt, 1.f);
    }
}

// ---------------- host orchestration ----------------
extern "C" void kernel_launch(void* const* d_in, const int* in_sizes, int n_in,
                              void* d_out, int out_size) {
    const int* x_l     = (const int*)d_in[0];
    const int* edge_l  = (const int*)d_in[1];
    const int* batch_l = (const int*)d_in[2];
    const int* x_r     = (const int*)d_in[3];
    const int* edge_r  = (const int*)d_in[4];
    const int* batch_r = (const int*)d_in[5];
    const float* emb = (const float*)d_in[6];
    const float* W1  = (const float*)d_in[7];  const float* as1 = (const float*)d_in[8];
    const float* ad1 = (const float*)d_in[9];  const float* b1  = (const float*)d_in[10];
    const float* lw1 = (const float*)d_in[11]; const float* lb1 = (const float*)d_in[12];
    const float* W2  = (const float*)d_in[13]; const float* as2 = (const float*)d_in[14];
    const float* ad2 = (const float*)d_in[15]; const float* b2  = (const float*)d_in[16];
    const float* lw2 = (const float*)d_in[17]; const float* lb2 = (const float*)d_in[18];
    const float* W3  = (const float*)d_in[19]; const float* as3 = (const float*)d_in[20];
    const float* ad3 = (const float*)d_in[21]; const float* b3  = (const float*)d_in[22];
    const float* lw3 = (const float*)d_in[23]; const float* lb3 = (const float*)d_in[24];
    float* out = (float*)d_out;

    __half* wh;
    cudaGetSymbolAddress((void**)&wh, g_wh);

    cudaFuncSetAttribute(k_fused, cudaFuncAttributeMaxDynamicSharedMemorySize, GEMM_SMEM);

    const int TB = 256;
    int init_grid = (2 * 2 * NNODES * 4 + TB - 1) / TB;
    if ((NWH + TB - 1) / TB > init_grid) init_grid = (NWH + TB - 1) / TB;

    k_init<<<init_grid, TB>>>(W2, lw2, W3, lw3, out);
    k_pre<<<VOCAB, 256>>>(emb, W1, lw1, as1, ad1);
    k_hist<<<dim3((NEDGES + TB - 1) / TB, 1, 2), TB>>>(edge_l, edge_r);
    k_scan_a<<<dim3(79, 1, 2), 256>>>();
    k_scan_b<<<2, 32>>>();
    k_scan_c<<<dim3(79, 1, 2), 256>>>();
    k_scatter<<<dim3((NEPLUS + TB - 1) / TB, 1, 2), TB>>>(edge_l, edge_r);
    k_l1gather<<<dim3((NNODES * 128 + TB - 1) / TB, 1, 2), TB>>>(x_l, x_r);

    const __half *W2h = wh, *lw2h = wh + 65536, *W3h = wh + 131072, *lw3h = wh + 262144;
    int GB2 = 4 * MBLK, GB3 = 5 * MBLK;

    // T1: gat1(L)
    k_gat_concat<<<GATBLK, TB>>>(0, 0, b1, lb1, 1);
    // T2: gemm2(L)+att2(L)  ||  gat1(R)
    k_fused<<<GB2 + GATBLK, TB, GEMM_SMEM>>>(0, 1, W2h, 256, lw2h, 256, 256, as2, ad2, 64,
                                             4, GB2, 1, 0, 0, b1, lb1, 1);
    // T3: gemm2(R)+att2(R)  ||  gat2(L)
    k_fused<<<GB2 + GATBLK, TB, GEMM_SMEM>>>(1, 1, W2h, 256, lw2h, 256, 256, as2, ad2, 64,
                                             4, GB2, 0, 1, 0, b2, lb2, 1);
    // T4: gemm3(L)+att3(L)  ||  gat2(R)
    k_fused<<<GB3 + GATBLK, TB, GEMM_SMEM>>>(0, 2, W3h, 512, lw3h, 128, 256, as3, ad3, 128,
                                             5, GB3, 1, 1, 0, b2, lb2, 1);
    // T5: gemm3(R)+att3(R)  ||  gat3(L) [mean]
    k_fused<<<GB3 + GATBLK, TB, GEMM_SMEM>>>(1, 2, W3h, 512, lw3h, 128, 256, as3, ad3, 128,
                                             5, GB3, 0, 2, 1, b3, lb3, 0);
    // T6: gat3(R) [mean]
    k_gat_mean<<<GATBLK, TB>>>(1, b3, lb3);

    // Pool
    k_pool_sum<<<dim3((NNODES + POOL_NB - 1) / POOL_NB, 1, 2), TB>>>(batch_l, batch_r, out);
    k_pool_div<<<(2 * NGRAPH * 128 + TB - 1) / TB, TB>>>(out);
}

// round 13
// speedup vs baseline: 1.2069x; 1.2069x over previous
#include <cuda_runtime.h>
#include <cuda_fp16.h>
#include <cstdint>

#define NNODES 20000
#define NEDGES 320000
#define NEPLUS 340000   // edges + self loops
#define NGRAPH 256
#define VOCAB  128
#define NWH    294912   // fp16 weights: W2(65536) lw2(65536) W3(131072) lw3(32768)
#define MBLK   157      // ceil(20000/128)
#define GATBLK 2500     // ceil(20000/8)

// ---------------- scratch (device globals; no runtime alloc allowed) ----------------
__device__ float  g_feat [2][NNODES * 128];  // layer-3 output (fp32, pooled)
__device__ __half g_feath[2][NNODES * 256];  // concat-layer outputs (GEMM inputs)
__device__ __half g_xh   [2][NNODES * 512];  // fp16 message features
__device__ float  g_lin  [2][NNODES * 256];
__device__ float  g_asb  [3][2][NNODES * 4]; // per-layer src scores (l0 store, l1/l2 atomic)
__device__ float  g_adb  [3][2][NNODES * 4];
__device__ float  g_exp  [2][NEPLUS * 4];    // cached per-edge exp
__device__ int    g_off  [2][NNODES + 1];
__device__ int    g_cur  [2][NNODES];
__device__ int    g_srcs [2][NEPLUS];
__device__ int    g_gcnt [2][NGRAPH];
__device__ int    g_bsum [2][128];
__device__ float  g_tab  [VOCAB * 512];
__device__ float  g_tatt [VOCAB * 8];
__device__ __half g_wh   [NWH];

__device__ __forceinline__ float lrelu(float x) { return x > 0.f ? x : 0.2f * x; }

__device__ __forceinline__ uint32_t sptr(const void* p) {
    return (uint32_t)__cvta_generic_to_shared(p);
}
#define CPA(dst, src, sz) \
    asm volatile("cp.async.cg.shared.global [%0], [%1], 16, %2;" :: "r"(dst), "l"(src), "r"(sz))
#define CP_COMMIT() asm volatile("cp.async.commit_group;" ::: "memory")
#define CP_WAIT1()  asm volatile("cp.async.wait_group 1;" ::: "memory")
#define CP_WAIT0()  asm volatile("cp.async.wait_group 0;" ::: "memory")

// ---------------- init: weight conversion + zero buffers + CSR counts ----------------
__global__ void k_init(const float* __restrict__ W2, const float* __restrict__ lw2,
                       const float* __restrict__ W3, const float* __restrict__ lw3,
                       float* out) {
    int i = blockIdx.x * blockDim.x + threadIdx.x;
    if (i < NWH) {
        float v;
        if (i < 65536)       v = W2[i];
        else if (i < 131072) v = lw2[i - 65536];
        else if (i < 262144) v = W3[i - 131072];
        else                 v = lw3[i - 262144];
        g_wh[i] = __float2half_rn(v);
    }
    if (i < 2 * NNODES) g_cur[i / NNODES][i % NNODES] = 1;
    if (i < 2 * NGRAPH * 128) out[i] = 0.f;
    if (i < 2 * NGRAPH) g_gcnt[i >> 8][i & 255] = 0;
    if (i < 2 * 2 * NNODES * 4) {
        int l = 1 + i / (2 * NNODES * 4);
        int r = i % (2 * NNODES * 4);
        g_asb[l][r / (NNODES * 4)][r % (NNODES * 4)] = 0.f;
        g_adb[l][r / (NNODES * 4)][r % (NNODES * 4)] = 0.f;
    }
}

// ---------------- layer-1 precompute: tables over the 128-entry vocab ----------------
__global__ void k_pre(const float* __restrict__ emb, const float* __restrict__ W1,
                      const float* __restrict__ lw1, const float* __restrict__ as1,
                      const float* __restrict__ ad1) {
    __shared__ float er[128];
    __shared__ float sAs[4], sAd[4];
    int v = blockIdx.x, t = threadIdx.x;  // 256 threads
    if (t < 128) er[t] = emb[v * 128 + t];
    if (t < 4) { sAs[t] = 0.f; sAd[t] = 0.f; }
    __syncthreads();
    float acc0 = 0.f, acc1 = 0.f;
    for (int k = 0; k < 128; k++) {
        float e = er[k];
        acc0 += e * W1[k * 256 + t];
        acc1 += e * lw1[k * 256 + t];
    }
    g_tab[v * 512 + t] = acc0;
    g_tab[v * 512 + 256 + t] = acc1;
    int h = t >> 6, c = t & 63;
    atomicAdd(&sAs[h], acc0 * as1[h * 64 + c]);
    atomicAdd(&sAd[h], acc0 * ad1[h * 64 + c]);
    __syncthreads();
    if (t < 4) { g_tatt[v * 8 + t] = sAs[t]; g_tatt[v * 8 + 4 + t] = sAd[t]; }
}

// ---------------- CSR build ----------------
__global__ void k_hist(const int* __restrict__ el, const int* __restrict__ er) {
    int side = blockIdx.z;
    const int* edge = side ? er : el;
    int e = blockIdx.x * blockDim.x + threadIdx.x;
    if (e < NEDGES) atomicAdd(&g_cur[side][edge[NEDGES + e]], 1);
}

__global__ void k_scan_a() {
    int side = blockIdx.z;
    __shared__ int sh[256];
    int t = threadIdx.x, i = blockIdx.x * 256 + t;
    int v = (i < NNODES) ? g_cur[side][i] : 0;
    sh[t] = v;
    __syncthreads();
    for (int o = 1; o < 256; o <<= 1) {
        int x = (t >= o) ? sh[t - o] : 0;
        __syncthreads();
        sh[t] += x;
        __syncthreads();
    }
    if (i < NNODES) g_off[side][i] = sh[t] - v;
    if (t == 255) g_bsum[side][blockIdx.x] = sh[255];
}
__global__ void k_scan_b() {
    int side = blockIdx.x, lane = threadIdx.x;
    int v[3]; int s = 0;
#pragma unroll
    for (int j = 0; j < 3; j++) {
        int b = lane * 3 + j;
        v[j] = (b < 79) ? g_bsum[side][b] : 0;
        s += v[j];
    }
    int ps = s;
    for (int o = 1; o < 32; o <<= 1) {
        int u = __shfl_up_sync(0xffffffffu, ps, o);
        if (lane >= o) ps += u;
    }
    int run = ps - s;
#pragma unroll
    for (int j = 0; j < 3; j++) {
        int b = lane * 3 + j;
        if (b < 79) g_bsum[side][b] = run;
        run += v[j];
    }
}
__global__ void k_scan_c() {
    int side = blockIdx.z;
    int i = blockIdx.x * 256 + threadIdx.x;
    if (i < NNODES) {
        int o = g_off[side][i] + g_bsum[side][i >> 8];
        g_off[side][i] = o;
        g_cur[side][i] = o;
    }
    if (i == 0) g_off[side][NNODES] = NEPLUS;
}

__global__ void k_scatter(const int* __restrict__ el, const int* __restrict__ er) {
    int side = blockIdx.z;
    const int* edge = side ? er : el;
    int e = blockIdx.x * blockDim.x + threadIdx.x;
    if (e < NEPLUS) {
        int s, d;
        if (e < NEDGES) { s = edge[e]; d = edge[NEDGES + e]; }
        else            { s = d = e - NEDGES; }
        int p = atomicAdd(&g_cur[side][d], 1);
        g_srcs[side][p] = s;
    }
}

// ---------------- layer-1 "GEMM" via table gather ----------------
__global__ void k_l1gather(const int* __restrict__ xl, const int* __restrict__ xr) {
    int side = blockIdx.z;
    const int* xi = side ? xr : xl;
    int idx = blockIdx.x * blockDim.x + threadIdx.x;
    if (idx >= NNODES * 128) return;
    int n = idx >> 7, q = idx & 127;
    int v = xi[n];
    float4 val = *(const float4*)(g_tab + v * 512 + q * 4);
    if (q < 64) {
        __half2 h0 = __floats2half2_rn(val.x, val.y);
        __half2 h1 = __floats2half2_rn(val.z, val.w);
        uint2 u = make_uint2(*(uint32_t*)&h0, *(uint32_t*)&h1);
        *(uint2*)(&g_xh[side][n * 256 + q * 4]) = u;
    } else {
        *(float4*)(&g_lin[side][n * 256 + (q - 64) * 4]) = val;
    }
    if (q == 0) {
        *(float4*)(&g_asb[0][side][n * 4]) = *(const float4*)(g_tatt + v * 8);
        *(float4*)(&g_adb[0][side][n * 4]) = *(const float4*)(g_tatt + v * 8 + 4);
    }
}

// ---------------- fp16 GEMM with fused attention-score epilogue ---------------------
__device__ __forceinline__ void mma_f16(float* c, const unsigned* a, const unsigned* b) {
    asm volatile(
        "mma.sync.aligned.m16n8k16.row.col.f32.f16.f16.f32 "
        "{%0,%1,%2,%3},{%4,%5,%6,%7},{%8,%9},{%0,%1,%2,%3};"
        : "+f"(c[0]), "+f"(c[1]), "+f"(c[2]), "+f"(c[3])
        : "r"(a[0]), "r"(a[1]), "r"(a[2]), "r"(a[3]),
          "r"(b[0]), "r"(b[1]));
}

#define AS_STRIDE 40
#define BS_STRIDE 136
#define GEMM_SMEM ((2 * 128 * AS_STRIDE + 2 * 32 * BS_STRIDE) * 2)

__global__ __launch_bounds__(256) void k_gemm(
    int layer,
    const __half* __restrict__ B1, int N1,
    const __half* __restrict__ B2, int N2,
    int K, const float* __restrict__ atts, const float* __restrict__ attd, int C) {
    extern __shared__ __half smh[];
    __half (*As)[128][AS_STRIDE] = (__half (*)[128][AS_STRIDE])smh;
    __half (*Bs)[32][BS_STRIDE] = (__half (*)[32][BS_STRIDE])(smh + 2 * 128 * AS_STRIDE);

    int side = blockIdx.z;
    int bx = blockIdx.x, by = blockIdx.y;
    const int M = NNODES;
    const __half* A = g_feath[side];
    int t1 = N1 >> 7;
    bool ishalf = (bx < t1);
    const __half* B; int N, n0;
    __half* Ch = g_xh[side];
    float* Cf = g_lin[side];
    if (ishalf) { B = B1; N = N1; n0 = bx << 7; }
    else        { B = B2; N = N2; n0 = (bx - t1) << 7; }

    int tid = threadIdx.x;
    int warp = tid >> 5, lane = tid & 31;
    int m0 = by * 128;
    int wm = (warp >> 2) * 64;
    int wn = (warp & 3) * 32;
    int gid = lane >> 2, tig = lane & 3;

    float c[4][4][4];
#pragma unroll
    for (int i = 0; i < 4; i++)
#pragma unroll
        for (int j = 0; j < 4; j++)
#pragma unroll
            for (int r = 0; r < 4; r++) c[i][j][r] = 0.f;

    auto load_tile = [&](int s, int kk) {
#pragma unroll
        for (int i = 0; i < 2; i++) {
            int cid = tid + 256 * i;
            int row = cid >> 2, coff = (cid & 3) * 8;
            const __half* asrc = A + (size_t)(m0 + row) * K + kk + coff;
            int sz = (m0 + row < M) ? 16 : 0;
            if (!sz) asrc = A;
            CPA(sptr(&As[s][row][coff]), asrc, sz);
            int krow = cid >> 4, noff = (cid & 15) * 8;
            const __half* bsrc = B + (size_t)(kk + krow) * N + n0 + noff;
            CPA(sptr(&Bs[s][krow][noff]), bsrc, 16);
        }
        CP_COMMIT();
    };

    auto compute = [&](int s) {
#pragma unroll
        for (int ks = 0; ks < 2; ks++) {
            unsigned a[4][4], b[4][2];
#pragma unroll
            for (int mi = 0; mi < 4; mi++) {
                uint32_t addr = sptr(&As[s][wm + mi * 16 + (lane & 15)][ks * 16 + (lane >> 4) * 8]);
                asm volatile("ldmatrix.sync.aligned.m8n8.x4.shared.b16 {%0,%1,%2,%3}, [%4];"
                             : "=r"(a[mi][0]), "=r"(a[mi][1]), "=r"(a[mi][2]), "=r"(a[mi][3])
                             : "r"(addr));
            }
#pragma unroll
            for (int ni = 0; ni < 4; ni++) {
                uint32_t addr = sptr(&Bs[s][ks * 16 + (lane & 15)][wn + ni * 8]);
                asm volatile("ldmatrix.sync.aligned.m8n8.x2.trans.shared.b16 {%0,%1}, [%2];"
                             : "=r"(b[ni][0]), "=r"(b[ni][1])
                             : "r"(addr));
            }
#pragma unroll
            for (int mi = 0; mi < 4; mi++)
#pragma unroll
                for (int ni = 0; ni < 4; ni++) mma_f16(c[mi][ni], a[mi], b[ni]);
        }
    };

    int KT = K >> 5;
    load_tile(0, 0);
    for (int kt = 0; kt < KT; kt++) {
        if (kt + 1 < KT) {
            load_tile((kt + 1) & 1, (kt + 1) << 5);
            CP_WAIT1();
        } else {
            CP_WAIT0();
        }
        __syncthreads();
        compute(kt & 1);
        __syncthreads();
    }
#pragma unroll
    for (int mi = 0; mi < 4; mi++) {
#pragma unroll
        for (int ni = 0; ni < 4; ni++) {
            int r0 = m0 + wm + mi * 16 + gid;
            int cc = n0 + wn + ni * 8 + tig * 2;
            if (ishalf) {
                if (r0 < M)
                    *(__half2*)(Ch + (size_t)r0 * N + cc) =
                        __floats2half2_rn(c[mi][ni][0], c[mi][ni][1]);
                if (r0 + 8 < M)
                    *(__half2*)(Ch + (size_t)(r0 + 8) * N + cc) =
                        __floats2half2_rn(c[mi][ni][2], c[mi][ni][3]);
            } else {
                if (r0 < M)
                    *(float2*)(Cf + (size_t)r0 * N + cc) = make_float2(c[mi][ni][0], c[mi][ni][1]);
                if (r0 + 8 < M)
                    *(float2*)(Cf + (size_t)(r0 + 8) * N + cc) = make_float2(c[mi][ni][2], c[mi][ni][3]);
            }
        }
    }
    // ---- fused attention-score epilogue (xh blocks only) ----
    if (ishalf) {
        int h = (n0 + wn) / C;   // warp's 32 cols lie within one head
        float av0[4], av1[4], bv0[4], bv1[4];
#pragma unroll
        for (int ni = 0; ni < 4; ni++) {
            int cc = n0 + wn + ni * 8 + tig * 2;
            av0[ni] = atts[cc]; av1[ni] = atts[cc + 1];
            bv0[ni] = attd[cc]; bv1[ni] = attd[cc + 1];
        }
        float* asb = g_asb[layer][side];
        float* adb = g_adb[layer][side];
#pragma unroll
        for (int mi = 0; mi < 4; mi++) {
            float s0 = 0.f, s1 = 0.f, d0 = 0.f, d1 = 0.f;
#pragma unroll
            for (int ni = 0; ni < 4; ni++) {
                s0 += c[mi][ni][0] * av0[ni] + c[mi][ni][1] * av1[ni];
                s1 += c[mi][ni][2] * av0[ni] + c[mi][ni][3] * av1[ni];
                d0 += c[mi][ni][0] * bv0[ni] + c[mi][ni][1] * bv1[ni];
                d1 += c[mi][ni][2] * bv0[ni] + c[mi][ni][3] * bv1[ni];
            }
#pragma unroll
            for (int o = 1; o <= 2; o <<= 1) {
                s0 += __shfl_xor_sync(0xffffffffu, s0, o);
                s1 += __shfl_xor_sync(0xffffffffu, s1, o);
                d0 += __shfl_xor_sync(0xffffffffu, d0, o);
                d1 += __shfl_xor_sync(0xffffffffu, d1, o);
            }
            if (tig == 0) {
                int r0 = m0 + wm + mi * 16 + gid;
                if (r0 < M) {
                    atomicAdd(&asb[r0 * 4 + h], s0);
                    atomicAdd(&adb[r0 * 4 + h], d0);
                }
                if (r0 + 8 < M) {
                    atomicAdd(&asb[(r0 + 8) * 4 + h], s1);
                    atomicAdd(&adb[(r0 + 8) * 4 + h], d1);
                }
            }
        }
    }
}

// ---------------- GAT kernels (standalone, zero dynamic smem, full occupancy) -------
__global__ __launch_bounds__(256) void k_gat_concat(
    int layer, const float* __restrict__ bias, const float* __restrict__ lbias,
    int relu_flag) {
    int side = blockIdx.z;
    int i = blockIdx.x * 8 + (threadIdx.x >> 5);
    int lane = threadIdx.x & 31;
    if (i >= NNODES) return;
    int beg = g_off[side][i], end = g_off[side][i + 1];
    const float* asbuf = g_asb[layer][side];
    float4 ad = *(const float4*)(&g_adb[layer][side][(size_t)i * 4]);
    float z0 = 0.f, z1 = 0.f, z2 = 0.f, z3 = 0.f;
    for (int e = beg + lane; e < end; e += 32) {
        int s = g_srcs[side][e];
        float4 as = *(const float4*)(&asbuf[(size_t)s * 4]);
        float e0 = __expf(fminf(lrelu(as.x + ad.x), 80.f));
        float e1 = __expf(fminf(lrelu(as.y + ad.y), 80.f));
        float e2 = __expf(fminf(lrelu(as.z + ad.z), 80.f));
        float e3 = __expf(fminf(lrelu(as.w + ad.w), 80.f));
        *(float4*)(&g_exp[side][(size_t)e * 4]) = make_float4(e0, e1, e2, e3);
        z0 += e0; z1 += e1; z2 += e2; z3 += e3;
    }
    for (int o = 16; o; o >>= 1) {
        z0 += __shfl_xor_sync(0xffffffffu, z0, o);
        z1 += __shfl_xor_sync(0xffffffffu, z1, o);
        z2 += __shfl_xor_sync(0xffffffffu, z2, o);
        z3 += __shfl_xor_sync(0xffffffffu, z3, o);
    }
    float i0 = 1.f / (z0 + 1e-16f), i1 = 1.f / (z1 + 1e-16f);
    float i2 = 1.f / (z2 + 1e-16f), i3 = 1.f / (z3 + 1e-16f);
    int h = lane >> 3;
    float myinv = (h == 0) ? i0 : (h == 1) ? i1 : (h == 2) ? i2 : i3;
    int col = lane * 8;
    float a0 = 0.f, a1 = 0.f, a2 = 0.f, a3 = 0.f, a4 = 0.f, a5 = 0.f, a6 = 0.f, a7 = 0.f;
    for (int e = beg; e < end; e++) {
        int s = g_srcs[side][e];
        float w = g_exp[side][(size_t)e * 4 + h] * myinv;
        uint4 u = *(const uint4*)(g_xh[side] + (size_t)s * 256 + col);
        __half2* hp = (__half2*)&u;
        float2 f0 = __half22float2(hp[0]);
        float2 f1 = __half22float2(hp[1]);
        float2 f2 = __half22float2(hp[2]);
        float2 f3 = __half22float2(hp[3]);
        a0 += w * f0.x; a1 += w * f0.y; a2 += w * f1.x; a3 += w * f1.y;
        a4 += w * f2.x; a5 += w * f2.y; a6 += w * f3.x; a7 += w * f3.y;
    }
    float4 lr0 = *(const float4*)(g_lin[side] + (size_t)i * 256 + col);
    float4 lr1 = *(const float4*)(g_lin[side] + (size_t)i * 256 + col + 4);
    float4 b0 = *(const float4*)(bias + col);
    float4 b1 = *(const float4*)(bias + col + 4);
    float4 lb0 = *(const float4*)(lbias + col);
    float4 lb1 = *(const float4*)(lbias + col + 4);
    float o0x = a0 + b0.x + lr0.x + lb0.x, o0y = a1 + b0.y + lr0.y + lb0.y;
    float o0z = a2 + b0.z + lr0.z + lb0.z, o0w = a3 + b0.w + lr0.w + lb0.w;
    float o1x = a4 + b1.x + lr1.x + lb1.x, o1y = a5 + b1.y + lr1.y + lb1.y;
    float o1z = a6 + b1.z + lr1.z + lb1.z, o1w = a7 + b1.w + lr1.w + lb1.w;
    if (relu_flag) {
        o0x = fmaxf(o0x, 0.f); o0y = fmaxf(o0y, 0.f);
        o0z = fmaxf(o0z, 0.f); o0w = fmaxf(o0w, 0.f);
        o1x = fmaxf(o1x, 0.f); o1y = fmaxf(o1y, 0.f);
        o1z = fmaxf(o1z, 0.f); o1w = fmaxf(o1w, 0.f);
    }
    __half2 h0 = __floats2half2_rn(o0x, o0y);
    __half2 h1 = __floats2half2_rn(o0z, o0w);
    __half2 h2 = __floats2half2_rn(o1x, o1y);
    __half2 h3 = __floats2half2_rn(o1z, o1w);
    uint4 uo = make_uint4(*(uint32_t*)&h0, *(uint32_t*)&h1, *(uint32_t*)&h2, *(uint32_t*)&h3);
    *(uint4*)(&g_feath[side][(size_t)i * 256 + col]) = uo;
}

__global__ __launch_bounds__(256) void k_gat_mean(
    const float* __restrict__ bias, const float* __restrict__ lbias) {
    int side = blockIdx.z;
    int i = blockIdx.x * 8 + (threadIdx.x >> 5);
    int lane = threadIdx.x & 31;
    if (i >= NNODES) return;
    int beg = g_off[side][i], end = g_off[side][i + 1];
    const float* asbuf = g_asb[2][side];
    float4 ad = *(const float4*)(&g_adb[2][side][(size_t)i * 4]);
    float z0 = 0.f, z1 = 0.f, z2 = 0.f, z3 = 0.f;
    for (int e = beg + lane; e < end; e += 32) {
        int s = g_srcs[side][e];
        float4 as = *(const float4*)(&asbuf[(size_t)s * 4]);
        float e0 = __expf(fminf(lrelu(as.x + ad.x), 80.f));
        float e1 = __expf(fminf(lrelu(as.y + ad.y), 80.f));
        float e2 = __expf(fminf(lrelu(as.z + ad.z), 80.f));
        float e3 = __expf(fminf(lrelu(as.w + ad.w), 80.f));
        *(float4*)(&g_exp[side][(size_t)e * 4]) = make_float4(e0, e1, e2, e3);
        z0 += e0; z1 += e1; z2 += e2; z3 += e3;
    }
    for (int o = 16; o; o >>= 1) {
        z0 += __shfl_xor_sync(0xffffffffu, z0, o);
        z1 += __shfl_xor_sync(0xffffffffu, z1, o);
        z2 += __shfl_xor_sync(0xffffffffu, z2, o);
        z3 += __shfl_xor_sync(0xffffffffu, z3, o);
    }
    float i0 = 1.f / (z0 + 1e-16f), i1 = 1.f / (z1 + 1e-16f);
    float i2 = 1.f / (z2 + 1e-16f), i3 = 1.f / (z3 + 1e-16f);
    int h = lane >> 3;
    float myinv = (h == 0) ? i0 : (h == 1) ? i1 : (h == 2) ? i2 : i3;
    int col = lane * 16;
    float acc[16];
#pragma unroll
    for (int j = 0; j < 16; j++) acc[j] = 0.f;
    for (int e = beg; e < end; e++) {
        int s = g_srcs[side][e];
        float w = g_exp[side][(size_t)e * 4 + h] * myinv;
        const uint4* xr = (const uint4*)(g_xh[side] + (size_t)s * 512 + col);
        uint4 u0 = xr[0], u1 = xr[1];
        __half2* hp0 = (__half2*)&u0;
        __half2* hp1 = (__half2*)&u1;
#pragma unroll
        for (int j = 0; j < 4; j++) {
            float2 f = __half22float2(hp0[j]);
            acc[j * 2] += w * f.x; acc[j * 2 + 1] += w * f.y;
        }
#pragma unroll
        for (int j = 0; j < 4; j++) {
            float2 f = __half22float2(hp1[j]);
            acc[8 + j * 2] += w * f.x; acc[8 + j * 2 + 1] += w * f.y;
        }
    }
#pragma unroll
    for (int mask = 8; mask <= 16; mask <<= 1)
#pragma unroll
        for (int j = 0; j < 16; j++)
            acc[j] += __shfl_xor_sync(0xffffffffu, acc[j], mask);
    if (lane < 8) {
        int c0 = lane * 16;
#pragma unroll
        for (int j = 0; j < 4; j++) {
            int c = c0 + j * 4;
            float4 lr = *(const float4*)(g_lin[side] + (size_t)i * 128 + c);
            float4 bb = *(const float4*)(bias + c);
            float4 lb = *(const float4*)(lbias + c);
            float4 o;
            o.x = 0.25f * acc[j * 4 + 0] + bb.x + lr.x + lb.x;
            o.y = 0.25f * acc[j * 4 + 1] + bb.y + lr.y + lb.y;
            o.z = 0.25f * acc[j * 4 + 2] + bb.z + lr.z + lb.z;
            o.w = 0.25f * acc[j * 4 + 3] + bb.w + lr.w + lb.w;
            *(float4*)(g_feat[side] + (size_t)i * 128 + c) = o;
        }
    }
}

// ---------------- global mean pool ----------------
#define POOL_NB 64
__global__ void k_pool_sum(const int* __restrict__ bl, const int* __restrict__ br, float* out) {
    int side = blockIdx.z;
    const int* batch = side ? br : bl;
    float* po = out + side * NGRAPH * 128;
    int n0 = blockIdx.x * POOL_NB;
    int c = threadIdx.x & 127;
    int r = threadIdx.x >> 7;
    float acc = 0.f;
    int cur = -1, cnt = 0;
    for (int j = r; j < POOL_NB; j += 2) {
        int n = n0 + j;
        if (n >= NNODES) break;
        int b = batch[n];
        if (b != cur) {
            if (cur >= 0) {
                atomicAdd(&po[cur * 128 + c], acc);
                if (c == 0) atomicAdd(&g_gcnt[side][cur], cnt);
            }
            acc = 0.f; cnt = 0; cur = b;
        }
        acc += g_feat[side][(size_t)n * 128 + c];
        cnt++;
    }
    if (cur >= 0) {
        atomicAdd(&po[cur * 128 + c], acc);
        if (c == 0) atomicAdd(&g_gcnt[side][cur], cnt);
    }
}
__global__ void k_pool_div(float* out) {
    int i = blockIdx.x * blockDim.x + threadIdx.x;
    if (i < 2 * NGRAPH * 128) {
        int side = i >> 15;
        float cnt = (float)g_gcnt[side][(i >> 7) & 255];
        out[i] /= fmaxf(cnt, 1.f);
    }
}

// ---------------- host orchestration ----------------
extern "C" void kernel_launch(void* const* d_in, const int* in_sizes, int n_in,
                              void* d_out, int out_size) {
    const int* x_l     = (const int*)d_in[0];
    const int* edge_l  = (const int*)d_in[1];
    const int* batch_l = (const int*)d_in[2];
    const int* x_r     = (const int*)d_in[3];
    const int* edge_r  = (const int*)d_in[4];
    const int* batch_r = (const int*)d_in[5];
    const float* emb = (const float*)d_in[6];
    const float* W1  = (const float*)d_in[7];  const float* as1 = (const float*)d_in[8];
    const float* ad1 = (const float*)d_in[9];  const float* b1  = (const float*)d_in[10];
    const float* lw1 = (const float*)d_in[11]; const float* lb1 = (const float*)d_in[12];
    const float* W2  = (const float*)d_in[13]; const float* as2 = (const float*)d_in[14];
    const float* ad2 = (const float*)d_in[15]; const float* b2  = (const float*)d_in[16];
    const float* lw2 = (const float*)d_in[17]; const float* lb2 = (const float*)d_in[18];
    const float* W3  = (const float*)d_in[19]; const float* as3 = (const float*)d_in[20];
    const float* ad3 = (const float*)d_in[21]; const float* b3  = (const float*)d_in[22];
    const float* lw3 = (const float*)d_in[23]; const float* lb3 = (const float*)d_in[24];
    float* out = (float*)d_out;

    __half* wh;
    cudaGetSymbolAddress((void**)&wh, g_wh);

    cudaFuncSetAttribute(k_gemm, cudaFuncAttributeMaxDynamicSharedMemorySize, GEMM_SMEM);

    const int TB = 256;
    int init_grid = (2 * 2 * NNODES * 4 + TB - 1) / TB;
    if ((NWH + TB - 1) / TB > init_grid) init_grid = (NWH + TB - 1) / TB;

    k_init<<<init_grid, TB>>>(W2, lw2, W3, lw3, out);
    k_pre<<<VOCAB, 256>>>(emb, W1, lw1, as1, ad1);
    k_hist<<<dim3((NEDGES + TB - 1) / TB, 1, 2), TB>>>(edge_l, edge_r);
    k_scan_a<<<dim3(79, 1, 2), 256>>>();
    k_scan_b<<<2, 32>>>();
    k_scan_c<<<dim3(79, 1, 2), 256>>>();
    k_scatter<<<dim3((NEPLUS + TB - 1) / TB, 1, 2), TB>>>(edge_l, edge_r);
    k_l1gather<<<dim3((NNODES * 128 + TB - 1) / TB, 1, 2), TB>>>(x_l, x_r);

    const __half *W2h = wh, *lw2h = wh + 65536, *W3h = wh + 131072, *lw3h = wh + 262144;

    // Layer 1: table gather already produced xh/lin/scores
    k_gat_concat<<<dim3(GATBLK, 1, 2), TB>>>(0, b1, lb1, 1);

    // Layer 2 (256 -> 256): GEMM + fused att scores, then GAT
    k_gemm<<<dim3(4, MBLK, 2), 256, GEMM_SMEM>>>(1, W2h, 256, lw2h, 256, 256, as2, ad2, 64);
    k_gat_concat<<<dim3(GATBLK, 1, 2), TB>>>(1, b2, lb2, 1);

    // Layer 3 (256 -> 512 xh / 128 lin): GEMM + fused att scores, then GAT mean
    k_gemm<<<dim3(5, MBLK, 2), 256, GEMM_SMEM>>>(2, W3h, 512, lw3h, 128, 256, as3, ad3, 128);
    k_gat_mean<<<dim3(GATBLK, 1, 2), TB>>>(b3, lb3);

    // Pool
    k_pool_sum<<<dim3((NNODES + POOL_NB - 1) / POOL_NB, 1, 2), TB>>>(batch_l, batch_r, out);
    k_pool_div<<<(2 * NGRAPH * 128 + TB - 1) / TB, TB>>>(out);
}

// round 14
// speedup vs baseline: 1.2364x; 1.0245x over previous
#include <cuda_runtime.h>
#include <cuda_fp16.h>
#include <cstdint>

#define NNODES 20000
#define NEDGES 320000
#define NEPLUS 340000   // edges + self loops
#define NGRAPH 256
#define VOCAB  128
#define NWH    294912   // fp16 weights: W2(65536) lw2(65536) W3(131072) lw3(32768)
#define MBLK   157      // ceil(20000/128)
#define GATBLK 2500     // ceil(20000/8)
#define HISTBLK 1250    // ceil(NEDGES/256)
#define SCATBLK 1329    // ceil(NEPLUS/256)
#define L1BLK   10000   // NNODES*128/256

// ---------------- scratch (device globals; no runtime alloc allowed) ----------------
__device__ float  g_feat [2][NNODES * 128];
__device__ __half g_feath[2][NNODES * 256];
__device__ __half g_xh   [2][NNODES * 512];
__device__ float  g_lin  [2][NNODES * 256];
__device__ float  g_asb  [3][2][NNODES * 4];
__device__ float  g_adb  [3][2][NNODES * 4];
__device__ float  g_exp  [2][NEPLUS * 4];
__device__ int    g_off  [2][NNODES + 1];
__device__ int    g_cur  [2][NNODES];
__device__ int    g_srcs [2][NEPLUS];
__device__ int    g_gcnt [2][NGRAPH];
__device__ int    g_bsum [2][128];
__device__ float  g_tab  [VOCAB * 512];
__device__ float  g_tatt [VOCAB * 8];
__device__ __half g_wh   [NWH];

__device__ __forceinline__ float lrelu(float x) { return x > 0.f ? x : 0.2f * x; }

__device__ __forceinline__ uint32_t sptr(const void* p) {
    return (uint32_t)__cvta_generic_to_shared(p);
}
#define CPA(dst, src, sz) \
    asm volatile("cp.async.cg.shared.global [%0], [%1], 16, %2;" :: "r"(dst), "l"(src), "r"(sz))
#define CP_COMMIT() asm volatile("cp.async.commit_group;" ::: "memory")
#define CP_WAIT1()  asm volatile("cp.async.wait_group 1;" ::: "memory")
#define CP_WAIT0()  asm volatile("cp.async.wait_group 0;" ::: "memory")

// ---------------- init: weight conversion + zero buffers + CSR counts ----------------
__global__ void k_init(const float* __restrict__ W2, const float* __restrict__ lw2,
                       const float* __restrict__ W3, const float* __restrict__ lw3,
                       float* out) {
    int i = blockIdx.x * blockDim.x + threadIdx.x;
    if (i < NWH) {
        float v;
        if (i < 65536)       v = W2[i];
        else if (i < 131072) v = lw2[i - 65536];
        else if (i < 262144) v = W3[i - 131072];
        else                 v = lw3[i - 262144];
        g_wh[i] = __float2half_rn(v);
    }
    if (i < 2 * NNODES) g_cur[i / NNODES][i % NNODES] = 1;
    if (i < 2 * NGRAPH * 128) out[i] = 0.f;
    if (i < 2 * NGRAPH) g_gcnt[i >> 8][i & 255] = 0;
    if (i < 2 * 2 * NNODES * 4) {
        int l = 1 + i / (2 * NNODES * 4);
        int r = i % (2 * NNODES * 4);
        g_asb[l][r / (NNODES * 4)][r % (NNODES * 4)] = 0.f;
        g_adb[l][r / (NNODES * 4)][r % (NNODES * 4)] = 0.f;
    }
}

// ---------------- FUSED: layer-1 table precompute + edge histogram ------------------
__global__ void k_pre_hist(const float* __restrict__ emb, const float* __restrict__ W1,
                           const float* __restrict__ lw1, const float* __restrict__ as1,
                           const float* __restrict__ ad1,
                           const int* __restrict__ el, const int* __restrict__ er) {
    __shared__ float er_s[128];
    __shared__ float sAs[4], sAd[4];
    int t = threadIdx.x;
    if ((int)blockIdx.x < VOCAB) {
        int v = blockIdx.x;
        if (t < 128) er_s[t] = emb[v * 128 + t];
        if (t < 4) { sAs[t] = 0.f; sAd[t] = 0.f; }
        __syncthreads();
        float acc0 = 0.f, acc1 = 0.f;
        for (int k = 0; k < 128; k++) {
            float e = er_s[k];
            acc0 += e * W1[k * 256 + t];
            acc1 += e * lw1[k * 256 + t];
        }
        g_tab[v * 512 + t] = acc0;
        g_tab[v * 512 + 256 + t] = acc1;
        int h = t >> 6, c = t & 63;
        atomicAdd(&sAs[h], acc0 * as1[h * 64 + c]);
        atomicAdd(&sAd[h], acc0 * ad1[h * 64 + c]);
        __syncthreads();
        if (t < 4) { g_tatt[v * 8 + t] = sAs[t]; g_tatt[v * 8 + 4 + t] = sAd[t]; }
    } else {
        int j = (blockIdx.x - VOCAB) * 256 + t;   // [0, 2*NEDGES)
        if (j < 2 * NEDGES) {
            int side = j / NEDGES;
            int e = j - side * NEDGES;
            const int* edge = side ? er : el;
            atomicAdd(&g_cur[side][edge[NEDGES + e]], 1);
        }
    }
}

// ---------------- scan: block-local (a), then self-basing apply (c) -----------------
__global__ void k_scan_a() {
    int side = blockIdx.z;
    __shared__ int sh[256];
    int t = threadIdx.x, i = blockIdx.x * 256 + t;
    int v = (i < NNODES) ? g_cur[side][i] : 0;
    sh[t] = v;
    __syncthreads();
    for (int o = 1; o < 256; o <<= 1) {
        int x = (t >= o) ? sh[t - o] : 0;
        __syncthreads();
        sh[t] += x;
        __syncthreads();
    }
    if (i < NNODES) g_off[side][i] = sh[t] - v;   // exclusive within block
    if (t == 255) g_bsum[side][blockIdx.x] = sh[255];  // raw block total
}
__global__ void k_scan_c() {   // each block sums bsum[0..bx) itself (79 L2-hot ints)
    int side = blockIdx.z;
    int bx = blockIdx.x, t = threadIdx.x;
    __shared__ int sbase;
    if (t < 32) {
        int s = 0;
        for (int j = t; j < 79; j += 32)
            if (j < bx) s += g_bsum[side][j];
        for (int o = 16; o; o >>= 1) s += __shfl_xor_sync(0xffffffffu, s, o);
        if (t == 0) sbase = s;
    }
    __syncthreads();
    int base = sbase;
    int i = bx * 256 + t;
    if (i < NNODES) {
        int o = g_off[side][i] + base;
        g_off[side][i] = o;
        g_cur[side][i] = o;
    }
    if (i == 0) g_off[side][NNODES] = NEPLUS;
}

// ---------------- FUSED: edge scatter + layer-1 table gather ------------------------
__global__ void k_scat_l1(const int* __restrict__ el, const int* __restrict__ er,
                          const int* __restrict__ xl, const int* __restrict__ xr) {
    int t = threadIdx.x;
    if ((int)blockIdx.x < 2 * SCATBLK) {
        int side = blockIdx.x / SCATBLK;
        int e = (blockIdx.x - side * SCATBLK) * 256 + t;
        if (e < NEPLUS) {
            const int* edge = side ? er : el;
            int s, d;
            if (e < NEDGES) { s = edge[e]; d = edge[NEDGES + e]; }
            else            { s = d = e - NEDGES; }
            int p = atomicAdd(&g_cur[side][d], 1);
            g_srcs[side][p] = s;
        }
    } else {
        int j = (blockIdx.x - 2 * SCATBLK);
        int side = j / L1BLK;
        int idx = (j - side * L1BLK) * 256 + t;
        const int* xi = side ? xr : xl;
        int n = idx >> 7, q = idx & 127;
        int v = xi[n];
        float4 val = *(const float4*)(g_tab + v * 512 + q * 4);
        if (q < 64) {
            __half2 h0 = __floats2half2_rn(val.x, val.y);
            __half2 h1 = __floats2half2_rn(val.z, val.w);
            uint2 u = make_uint2(*(uint32_t*)&h0, *(uint32_t*)&h1);
            *(uint2*)(&g_xh[side][n * 256 + q * 4]) = u;
        } else {
            *(float4*)(&g_lin[side][n * 256 + (q - 64) * 4]) = val;
        }
        if (q == 0) {
            *(float4*)(&g_asb[0][side][n * 4]) = *(const float4*)(g_tatt + v * 8);
            *(float4*)(&g_adb[0][side][n * 4]) = *(const float4*)(g_tatt + v * 8 + 4);
        }
    }
}

// ---------------- fp16 GEMM with fused attention-score epilogue ---------------------
__device__ __forceinline__ void mma_f16(float* c, const unsigned* a, const unsigned* b) {
    asm volatile(
        "mma.sync.aligned.m16n8k16.row.col.f32.f16.f16.f32 "
        "{%0,%1,%2,%3},{%4,%5,%6,%7},{%8,%9},{%0,%1,%2,%3};"
        : "+f"(c[0]), "+f"(c[1]), "+f"(c[2]), "+f"(c[3])
        : "r"(a[0]), "r"(a[1]), "r"(a[2]), "r"(a[3]),
          "r"(b[0]), "r"(b[1]));
}

#define AS_STRIDE 40
#define BS_STRIDE 136
#define GEMM_SMEM ((2 * 128 * AS_STRIDE + 2 * 32 * BS_STRIDE) * 2)

__global__ __launch_bounds__(256) void k_gemm(
    int layer,
    const __half* __restrict__ B1, int N1,
    const __half* __restrict__ B2, int N2,
    int K, const float* __restrict__ atts, const float* __restrict__ attd, int C) {
    extern __shared__ __half smh[];
    __half (*As)[128][AS_STRIDE] = (__half (*)[128][AS_STRIDE])smh;
    __half (*Bs)[32][BS_STRIDE] = (__half (*)[32][BS_STRIDE])(smh + 2 * 128 * AS_STRIDE);

    int side = blockIdx.z;
    int bx = blockIdx.x, by = blockIdx.y;
    const int M = NNODES;
    const __half* A = g_feath[side];
    int t1 = N1 >> 7;
    bool ishalf = (bx < t1);
    const __half* B; int N, n0;
    __half* Ch = g_xh[side];
    float* Cf = g_lin[side];
    if (ishalf) { B = B1; N = N1; n0 = bx << 7; }
    else        { B = B2; N = N2; n0 = (bx - t1) << 7; }

    int tid = threadIdx.x;
    int warp = tid >> 5, lane = tid & 31;
    int m0 = by * 128;
    int wm = (warp >> 2) * 64;
    int wn = (warp & 3) * 32;
    int gid = lane >> 2, tig = lane & 3;

    float c[4][4][4];
#pragma unroll
    for (int i = 0; i < 4; i++)
#pragma unroll
        for (int j = 0; j < 4; j++)
#pragma unroll
            for (int r = 0; r < 4; r++) c[i][j][r] = 0.f;

    auto load_tile = [&](int s, int kk) {
#pragma unroll
        for (int i = 0; i < 2; i++) {
            int cid = tid + 256 * i;
            int row = cid >> 2, coff = (cid & 3) * 8;
            const __half* asrc = A + (size_t)(m0 + row) * K + kk + coff;
            int sz = (m0 + row < M) ? 16 : 0;
            if (!sz) asrc = A;
            CPA(sptr(&As[s][row][coff]), asrc, sz);
            int krow = cid >> 4, noff = (cid & 15) * 8;
            const __half* bsrc = B + (size_t)(kk + krow) * N + n0 + noff;
            CPA(sptr(&Bs[s][krow][noff]), bsrc, 16);
        }
        CP_COMMIT();
    };

    auto compute = [&](int s) {
#pragma unroll
        for (int ks = 0; ks < 2; ks++) {
            unsigned a[4][4], b[4][2];
#pragma unroll
            for (int mi = 0; mi < 4; mi++) {
                uint32_t addr = sptr(&As[s][wm + mi * 16 + (lane & 15)][ks * 16 + (lane >> 4) * 8]);
                asm volatile("ldmatrix.sync.aligned.m8n8.x4.shared.b16 {%0,%1,%2,%3}, [%4];"
                             : "=r"(a[mi][0]), "=r"(a[mi][1]), "=r"(a[mi][2]), "=r"(a[mi][3])
                             : "r"(addr));
            }
#pragma unroll
            for (int ni = 0; ni < 4; ni++) {
                uint32_t addr = sptr(&Bs[s][ks * 16 + (lane & 15)][wn + ni * 8]);
                asm volatile("ldmatrix.sync.aligned.m8n8.x2.trans.shared.b16 {%0,%1}, [%2];"
                             : "=r"(b[ni][0]), "=r"(b[ni][1])
                             : "r"(addr));
            }
#pragma unroll
            for (int mi = 0; mi < 4; mi++)
#pragma unroll
                for (int ni = 0; ni < 4; ni++) mma_f16(c[mi][ni], a[mi], b[ni]);
        }
    };

    int KT = K >> 5;
    load_tile(0, 0);
    for (int kt = 0; kt < KT; kt++) {
        if (kt + 1 < KT) {
            load_tile((kt + 1) & 1, (kt + 1) << 5);
            CP_WAIT1();
        } else {
            CP_WAIT0();
        }
        __syncthreads();
        compute(kt & 1);
        __syncthreads();
    }
#pragma unroll
    for (int mi = 0; mi < 4; mi++) {
#pragma unroll
        for (int ni = 0; ni < 4; ni++) {
            int r0 = m0 + wm + mi * 16 + gid;
            int cc = n0 + wn + ni * 8 + tig * 2;
            if (ishalf) {
                if (r0 < M)
                    *(__half2*)(Ch + (size_t)r0 * N + cc) =
                        __floats2half2_rn(c[mi][ni][0], c[mi][ni][1]);
                if (r0 + 8 < M)
                    *(__half2*)(Ch + (size_t)(r0 + 8) * N + cc) =
                        __floats2half2_rn(c[mi][ni][2], c[mi][ni][3]);
            } else {
                if (r0 < M)
                    *(float2*)(Cf + (size_t)r0 * N + cc) = make_float2(c[mi][ni][0], c[mi][ni][1]);
                if (r0 + 8 < M)
                    *(float2*)(Cf + (size_t)(r0 + 8) * N + cc) = make_float2(c[mi][ni][2], c[mi][ni][3]);
            }
        }
    }
    // ---- fused attention-score epilogue (xh blocks only) ----
    if (ishalf) {
        int h = (n0 + wn) / C;
        float av0[4], av1[4], bv0[4], bv1[4];
#pragma unroll
        for (int ni = 0; ni < 4; ni++) {
            int cc = n0 + wn + ni * 8 + tig * 2;
            av0[ni] = atts[cc]; av1[ni] = atts[cc + 1];
            bv0[ni] = attd[cc]; bv1[ni] = attd[cc + 1];
        }
        float* asb = g_asb[layer][side];
        float* adb = g_adb[layer][side];
#pragma unroll
        for (int mi = 0; mi < 4; mi++) {
            float s0 = 0.f, s1 = 0.f, d0 = 0.f, d1 = 0.f;
#pragma unroll
            for (int ni = 0; ni < 4; ni++) {
                s0 += c[mi][ni][0] * av0[ni] + c[mi][ni][1] * av1[ni];
                s1 += c[mi][ni][2] * av0[ni] + c[mi][ni][3] * av1[ni];
                d0 += c[mi][ni][0] * bv0[ni] + c[mi][ni][1] * bv1[ni];
                d1 += c[mi][ni][2] * bv0[ni] + c[mi][ni][3] * bv1[ni];
            }
#pragma unroll
            for (int o = 1; o <= 2; o <<= 1) {
                s0 += __shfl_xor_sync(0xffffffffu, s0, o);
                s1 += __shfl_xor_sync(0xffffffffu, s1, o);
                d0 += __shfl_xor_sync(0xffffffffu, d0, o);
                d1 += __shfl_xor_sync(0xffffffffu, d1, o);
            }
            if (tig == 0) {
                int r0 = m0 + wm + mi * 16 + gid;
                if (r0 < M) {
                    atomicAdd(&asb[r0 * 4 + h], s0);
                    atomicAdd(&adb[r0 * 4 + h], d0);
                }
                if (r0 + 8 < M) {
                    atomicAdd(&asb[(r0 + 8) * 4 + h], s1);
                    atomicAdd(&adb[(r0 + 8) * 4 + h], d1);
                }
            }
        }
    }
}

// ---------------- GAT kernels (standalone, zero dynamic smem) ----------------
__global__ __launch_bounds__(256) void k_gat_concat(
    int layer, const float* __restrict__ bias, const float* __restrict__ lbias,
    int relu_flag) {
    int side = blockIdx.z;
    int i = blockIdx.x * 8 + (threadIdx.x >> 5);
    int lane = threadIdx.x & 31;
    if (i >= NNODES) return;
    int beg = g_off[side][i], end = g_off[side][i + 1];
    const float* asbuf = g_asb[layer][side];
    float4 ad = *(const float4*)(&g_adb[layer][side][(size_t)i * 4]);
    float z0 = 0.f, z1 = 0.f, z2 = 0.f, z3 = 0.f;
    for (int e = beg + lane; e < end; e += 32) {
        int s = g_srcs[side][e];
        float4 as = *(const float4*)(&asbuf[(size_t)s * 4]);
        float e0 = __expf(fminf(lrelu(as.x + ad.x), 80.f));
        float e1 = __expf(fminf(lrelu(as.y + ad.y), 80.f));
        float e2 = __expf(fminf(lrelu(as.z + ad.z), 80.f));
        float e3 = __expf(fminf(lrelu(as.w + ad.w), 80.f));
        *(float4*)(&g_exp[side][(size_t)e * 4]) = make_float4(e0, e1, e2, e3);
        z0 += e0; z1 += e1; z2 += e2; z3 += e3;
    }
    for (int o = 16; o; o >>= 1) {
        z0 += __shfl_xor_sync(0xffffffffu, z0, o);
        z1 += __shfl_xor_sync(0xffffffffu, z1, o);
        z2 += __shfl_xor_sync(0xffffffffu, z2, o);
        z3 += __shfl_xor_sync(0xffffffffu, z3, o);
    }
    float i0 = 1.f / (z0 + 1e-16f), i1 = 1.f / (z1 + 1e-16f);
    float i2 = 1.f / (z2 + 1e-16f), i3 = 1.f / (z3 + 1e-16f);
    int h = lane >> 3;
    float myinv = (h == 0) ? i0 : (h == 1) ? i1 : (h == 2) ? i2 : i3;
    int col = lane * 8;
    float a0 = 0.f, a1 = 0.f, a2 = 0.f, a3 = 0.f, a4 = 0.f, a5 = 0.f, a6 = 0.f, a7 = 0.f;
    for (int e = beg; e < end; e++) {
        int s = g_srcs[side][e];
        float w = g_exp[side][(size_t)e * 4 + h] * myinv;
        uint4 u = *(const uint4*)(g_xh[side] + (size_t)s * 256 + col);
        __half2* hp = (__half2*)&u;
        float2 f0 = __half22float2(hp[0]);
        float2 f1 = __half22float2(hp[1]);
        float2 f2 = __half22float2(hp[2]);
        float2 f3 = __half22float2(hp[3]);
        a0 += w * f0.x; a1 += w * f0.y; a2 += w * f1.x; a3 += w * f1.y;
        a4 += w * f2.x; a5 += w * f2.y; a6 += w * f3.x; a7 += w * f3.y;
    }
    float4 lr0 = *(const float4*)(g_lin[side] + (size_t)i * 256 + col);
    float4 lr1 = *(const float4*)(g_lin[side] + (size_t)i * 256 + col + 4);
    float4 b0 = *(const float4*)(bias + col);
    float4 b1 = *(const float4*)(bias + col + 4);
    float4 lb0 = *(const float4*)(lbias + col);
    float4 lb1 = *(const float4*)(lbias + col + 4);
    float o0x = a0 + b0.x + lr0.x + lb0.x, o0y = a1 + b0.y + lr0.y + lb0.y;
    float o0z = a2 + b0.z + lr0.z + lb0.z, o0w = a3 + b0.w + lr0.w + lb0.w;
    float o1x = a4 + b1.x + lr1.x + lb1.x, o1y = a5 + b1.y + lr1.y + lb1.y;
    float o1z = a6 + b1.z + lr1.z + lb1.z, o1w = a7 + b1.w + lr1.w + lb1.w;
    if (relu_flag) {
        o0x = fmaxf(o0x, 0.f); o0y = fmaxf(o0y, 0.f);
        o0z = fmaxf(o0z, 0.f); o0w = fmaxf(o0w, 0.f);
        o1x = fmaxf(o1x, 0.f); o1y = fmaxf(o1y, 0.f);
        o1z = fmaxf(o1z, 0.f); o1w = fmaxf(o1w, 0.f);
    }
    __half2 h0 = __floats2half2_rn(o0x, o0y);
    __half2 h1 = __floats2half2_rn(o0z, o0w);
    __half2 h2 = __floats2half2_rn(o1x, o1y);
    __half2 h3 = __floats2half2_rn(o1z, o1w);
    uint4 uo = make_uint4(*(uint32_t*)&h0, *(uint32_t*)&h1, *(uint32_t*)&h2, *(uint32_t*)&h3);
    *(uint4*)(&g_feath[side][(size_t)i * 256 + col]) = uo;
}

__global__ __launch_bounds__(256) void k_gat_mean(
    const float* __restrict__ bias, const float* __restrict__ lbias) {
    int side = blockIdx.z;
    int i = blockIdx.x * 8 + (threadIdx.x >> 5);
    int lane = threadIdx.x & 31;
    if (i >= NNODES) return;
    int beg = g_off[side][i], end = g_off[side][i + 1];
    const float* asbuf = g_asb[2][side];
    float4 ad = *(const float4*)(&g_adb[2][side][(size_t)i * 4]);
    float z0 = 0.f, z1 = 0.f, z2 = 0.f, z3 = 0.f;
    for (int e = beg + lane; e < end; e += 32) {
        int s = g_srcs[side][e];
        float4 as = *(const float4*)(&asbuf[(size_t)s * 4]);
        float e0 = __expf(fminf(lrelu(as.x + ad.x), 80.f));
        float e1 = __expf(fminf(lrelu(as.y + ad.y), 80.f));
        float e2 = __expf(fminf(lrelu(as.z + ad.z), 80.f));
        float e3 = __expf(fminf(lrelu(as.w + ad.w), 80.f));
        *(float4*)(&g_exp[side][(size_t)e * 4]) = make_float4(e0, e1, e2, e3);
        z0 += e0; z1 += e1; z2 += e2; z3 += e3;
    }
    for (int o = 16; o; o >>= 1) {
        z0 += __shfl_xor_sync(0xffffffffu, z0, o);
        z1 += __shfl_xor_sync(0xffffffffu, z1, o);
        z2 += __shfl_xor_sync(0xffffffffu, z2, o);
        z3 += __shfl_xor_sync(0xffffffffu, z3, o);
    }
    float i0 = 1.f / (z0 + 1e-16f), i1 = 1.f / (z1 + 1e-16f);
    float i2 = 1.f / (z2 + 1e-16f), i3 = 1.f / (z3 + 1e-16f);
    int h = lane >> 3;
    float myinv = (h == 0) ? i0 : (h == 1) ? i1 : (h == 2) ? i2 : i3;
    int col = lane * 16;
    float acc[16];
#pragma unroll
    for (int j = 0; j < 16; j++) acc[j] = 0.f;
    for (int e = beg; e < end; e++) {
        int s = g_srcs[side][e];
        float w = g_exp[side][(size_t)e * 4 + h] * myinv;
        const uint4* xr = (const uint4*)(g_xh[side] + (size_t)s * 512 + col);
        uint4 u0 = xr[0], u1 = xr[1];
        __half2* hp0 = (__half2*)&u0;
        __half2* hp1 = (__half2*)&u1;
#pragma unroll
        for (int j = 0; j < 4; j++) {
            float2 f = __half22float2(hp0[j]);
            acc[j * 2] += w * f.x; acc[j * 2 + 1] += w * f.y;
        }
#pragma unroll
        for (int j = 0; j < 4; j++) {
            float2 f = __half22float2(hp1[j]);
            acc[8 + j * 2] += w * f.x; acc[8 + j * 2 + 1] += w * f.y;
        }
    }
#pragma unroll
    for (int mask = 8; mask <= 16; mask <<= 1)
#pragma unroll
        for (int j = 0; j < 16; j++)
            acc[j] += __shfl_xor_sync(0xffffffffu, acc[j], mask);
    if (lane < 8) {
        int c0 = lane * 16;
#pragma unroll
        for (int j = 0; j < 4; j++) {
            int c = c0 + j * 4;
            float4 lr = *(const float4*)(g_lin[side] + (size_t)i * 128 + c);
            float4 bb = *(const float4*)(bias + c);
            float4 lb = *(const float4*)(lbias + c);
            float4 o;
            o.x = 0.25f * acc[j * 4 + 0] + bb.x + lr.x + lb.x;
            o.y = 0.25f * acc[j * 4 + 1] + bb.y + lr.y + lb.y;
            o.z = 0.25f * acc[j * 4 + 2] + bb.z + lr.z + lb.z;
            o.w = 0.25f * acc[j * 4 + 3] + bb.w + lr.w + lb.w;
            *(float4*)(g_feat[side] + (size_t)i * 128 + c) = o;
        }
    }
}

// ---------------- global mean pool ----------------
#define POOL_NB 64
__global__ void k_pool_sum(const int* __restrict__ bl, const int* __restrict__ br, float* out) {
    int side = blockIdx.z;
    const int* batch = side ? br : bl;
    float* po = out + side * NGRAPH * 128;
    int n0 = blockIdx.x * POOL_NB;
    int c = threadIdx.x & 127;
    int r = threadIdx.x >> 7;
    float acc = 0.f;
    int cur = -1, cnt = 0;
    for (int j = r; j < POOL_NB; j += 2) {
        int n = n0 + j;
        if (n >= NNODES) break;
        int b = batch[n];
        if (b != cur) {
            if (cur >= 0) {
                atomicAdd(&po[cur * 128 + c], acc);
                if (c == 0) atomicAdd(&g_gcnt[side][cur], cnt);
            }
            acc = 0.f; cnt = 0; cur = b;
        }
        acc += g_feat[side][(size_t)n * 128 + c];
        cnt++;
    }
    if (cur >= 0) {
        atomicAdd(&po[cur * 128 + c], acc);
        if (c == 0) atomicAdd(&g_gcnt[side][cur], cnt);
    }
}
__global__ void k_pool_div(float* out) {
    int i = blockIdx.x * blockDim.x + threadIdx.x;
    if (i < 2 * NGRAPH * 128) {
        int side = i >> 15;
        float cnt = (float)g_gcnt[side][(i >> 7) & 255];
        out[i] /= fmaxf(cnt, 1.f);
    }
}

// ---------------- host orchestration ----------------
extern "C" void kernel_launch(void* const* d_in, const int* in_sizes, int n_in,
                              void* d_out, int out_size) {
    const int* x_l     = (const int*)d_in[0];
    const int* edge_l  = (const int*)d_in[1];
    const int* batch_l = (const int*)d_in[2];
    const int* x_r     = (const int*)d_in[3];
    const int* edge_r  = (const int*)d_in[4];
    const int* batch_r = (const int*)d_in[5];
    const float* emb = (const float*)d_in[6];
    const float* W1  = (const float*)d_in[7];  const float* as1 = (const float*)d_in[8];
    const float* ad1 = (const float*)d_in[9];  const float* b1  = (const float*)d_in[10];
    const float* lw1 = (const float*)d_in[11]; const float* lb1 = (const float*)d_in[12];
    const float* W2  = (const float*)d_in[13]; const float* as2 = (const float*)d_in[14];
    const float* ad2 = (const float*)d_in[15]; const float* b2  = (const float*)d_in[16];
    const float* lw2 = (const float*)d_in[17]; const float* lb2 = (const float*)d_in[18];
    const float* W3  = (const float*)d_in[19]; const float* as3 = (const float*)d_in[20];
    const float* ad3 = (const float*)d_in[21]; const float* b3  = (const float*)d_in[22];
    const float* lw3 = (const float*)d_in[23]; const float* lb3 = (const float*)d_in[24];
    float* out = (float*)d_out;

    __half* wh;
    cudaGetSymbolAddress((void**)&wh, g_wh);

    cudaFuncSetAttribute(k_gemm, cudaFuncAttributeMaxDynamicSharedMemorySize, GEMM_SMEM);

    const int TB = 256;
    int init_grid = (2 * 2 * NNODES * 4 + TB - 1) / TB;
    if ((NWH + TB - 1) / TB > init_grid) init_grid = (NWH + TB - 1) / TB;

    k_init<<<init_grid, TB>>>(W2, lw2, W3, lw3, out);
    k_pre_hist<<<VOCAB + 2 * HISTBLK, TB>>>(emb, W1, lw1, as1, ad1, edge_l, edge_r);
    k_scan_a<<<dim3(79, 1, 2), 256>>>();
    k_scan_c<<<dim3(79, 1, 2), 256>>>();
    k_scat_l1<<<2 * SCATBLK + 2 * L1BLK, TB>>>(edge_l, edge_r, x_l, x_r);

    const __half *W2h = wh, *lw2h = wh + 65536, *W3h = wh + 131072, *lw3h = wh + 262144;

    // Layer 1
    k_gat_concat<<<dim3(GATBLK, 1, 2), TB>>>(0, b1, lb1, 1);
    // Layer 2
    k_gemm<<<dim3(4, MBLK, 2), 256, GEMM_SMEM>>>(1, W2h, 256, lw2h, 256, 256, as2, ad2, 64);
    k_gat_concat<<<dim3(GATBLK, 1, 2), TB>>>(1, b2, lb2, 1);
    // Layer 3
    k_gemm<<<dim3(5, MBLK, 2), 256, GEMM_SMEM>>>(2, W3h, 512, lw3h, 128, 256, as3, ad3, 128);
    k_gat_mean<<<dim3(GATBLK, 1, 2), TB>>>(b3, lb3);

    // Pool
    k_pool_sum<<<dim3((NNODES + POOL_NB - 1) / POOL_NB, 1, 2), TB>>>(batch_l, batch_r, out);
    k_pool_div<<<(2 * NGRAPH * 128 + TB - 1) / TB, TB>>>(out);
}

// round 15
// speedup vs baseline: 1.2725x; 1.0292x over previous
#include <cuda_runtime.h>
#include <cuda_fp16.h>
#include <cstdint>

#define NNODES 20000
#define NEDGES 320000
#define NEPLUS 340000   // edges + self loops
#define NGRAPH 256
#define VOCAB  128
#define NWH    294912   // fp16 weights: W2(65536) lw2(65536) W3(131072) lw3(32768)
#define MBLK   157      // ceil(20000/128)
#define GATBLK 2500     // ceil(20000/8)
#define HISTBLK 1250    // ceil(NEDGES/256)
#define SCATBLK 1329    // ceil(NEPLUS/256)
#define L1BLK   10000   // NNODES*128/256

// ---------------- scratch (device globals; no runtime alloc allowed) ----------------
__device__ float  g_feat [2][NNODES * 128];
__device__ __half g_feath[2][NNODES * 256];
__device__ __half g_xh   [2][NNODES * 512];
__device__ float  g_lin  [2][NNODES * 256];
__device__ float  g_asb  [3][2][NNODES * 4];
__device__ float  g_adb  [3][2][NNODES * 4];
__device__ float  g_exp  [2][NEPLUS * 4];
__device__ int    g_off  [2][NNODES + 1];
__device__ int    g_cur  [2][NNODES];
__device__ int    g_srcs [2][NEPLUS];
__device__ int    g_gcnt [2][NGRAPH];
__device__ int    g_bsum [2][128];
__device__ float  g_tab  [VOCAB * 512];
__device__ float  g_tatt [VOCAB * 8];
__device__ __half g_wh   [NWH];

__device__ __forceinline__ float lrelu(float x) { return x > 0.f ? x : 0.2f * x; }

__device__ __forceinline__ uint32_t sptr(const void* p) {
    return (uint32_t)__cvta_generic_to_shared(p);
}
#define CPA(dst, src, sz) \
    asm volatile("cp.async.cg.shared.global [%0], [%1], 16, %2;" :: "r"(dst), "l"(src), "r"(sz))
#define CP_COMMIT() asm volatile("cp.async.commit_group;" ::: "memory")
#define CP_WAIT1()  asm volatile("cp.async.wait_group 1;" ::: "memory")
#define CP_WAIT0()  asm volatile("cp.async.wait_group 0;" ::: "memory")

// ---------------- init ----------------
__global__ void k_init(const float* __restrict__ W2, const float* __restrict__ lw2,
                       const float* __restrict__ W3, const float* __restrict__ lw3,
                       float* out) {
    int i = blockIdx.x * blockDim.x + threadIdx.x;
    if (i < NWH) {
        float v;
        if (i < 65536)       v = W2[i];
        else if (i < 131072) v = lw2[i - 65536];
        else if (i < 262144) v = W3[i - 131072];
        else                 v = lw3[i - 262144];
        g_wh[i] = __float2half_rn(v);
    }
    if (i < 2 * NNODES) g_cur[i / NNODES][i % NNODES] = 1;
    if (i < 2 * NGRAPH * 128) out[i] = 0.f;
    if (i < 2 * NGRAPH) g_gcnt[i >> 8][i & 255] = 0;
    if (i < 2 * 2 * NNODES * 4) {
        int l = 1 + i / (2 * NNODES * 4);
        int r = i % (2 * NNODES * 4);
        g_asb[l][r / (NNODES * 4)][r % (NNODES * 4)] = 0.f;
        g_adb[l][r / (NNODES * 4)][r % (NNODES * 4)] = 0.f;
    }
}

// ---------------- FUSED: layer-1 table precompute + edge histogram ------------------
__global__ void k_pre_hist(const float* __restrict__ emb, const float* __restrict__ W1,
                           const float* __restrict__ lw1, const float* __restrict__ as1,
                           const float* __restrict__ ad1,
                           const int* __restrict__ el, const int* __restrict__ er) {
    __shared__ float er_s[128];
    __shared__ float sAs[4], sAd[4];
    int t = threadIdx.x;
    if ((int)blockIdx.x < VOCAB) {
        int v = blockIdx.x;
        if (t < 128) er_s[t] = emb[v * 128 + t];
        if (t < 4) { sAs[t] = 0.f; sAd[t] = 0.f; }
        __syncthreads();
        float acc0 = 0.f, acc1 = 0.f;
        for (int k = 0; k < 128; k++) {
            float e = er_s[k];
            acc0 += e * W1[k * 256 + t];
            acc1 += e * lw1[k * 256 + t];
        }
        g_tab[v * 512 + t] = acc0;
        g_tab[v * 512 + 256 + t] = acc1;
        int h = t >> 6, c = t & 63;
        atomicAdd(&sAs[h], acc0 * as1[h * 64 + c]);
        atomicAdd(&sAd[h], acc0 * ad1[h * 64 + c]);
        __syncthreads();
        if (t < 4) { g_tatt[v * 8 + t] = sAs[t]; g_tatt[v * 8 + 4 + t] = sAd[t]; }
    } else {
        int j = (blockIdx.x - VOCAB) * 256 + t;
        if (j < 2 * NEDGES) {
            int side = j / NEDGES;
            int e = j - side * NEDGES;
            const int* edge = side ? er : el;
            atomicAdd(&g_cur[side][edge[NEDGES + e]], 1);
        }
    }
}

// ---------------- scan ----------------
__global__ void k_scan_a() {
    int side = blockIdx.z;
    __shared__ int sh[256];
    int t = threadIdx.x, i = blockIdx.x * 256 + t;
    int v = (i < NNODES) ? g_cur[side][i] : 0;
    sh[t] = v;
    __syncthreads();
    for (int o = 1; o < 256; o <<= 1) {
        int x = (t >= o) ? sh[t - o] : 0;
        __syncthreads();
        sh[t] += x;
        __syncthreads();
    }
    if (i < NNODES) g_off[side][i] = sh[t] - v;
    if (t == 255) g_bsum[side][blockIdx.x] = sh[255];
}
__global__ void k_scan_c() {
    int side = blockIdx.z;
    int bx = blockIdx.x, t = threadIdx.x;
    __shared__ int sbase;
    if (t < 32) {
        int s = 0;
        for (int j = t; j < 79; j += 32)
            if (j < bx) s += g_bsum[side][j];
        for (int o = 16; o; o >>= 1) s += __shfl_xor_sync(0xffffffffu, s, o);
        if (t == 0) sbase = s;
    }
    __syncthreads();
    int base = sbase;
    int i = bx * 256 + t;
    if (i < NNODES) {
        int o = g_off[side][i] + base;
        g_off[side][i] = o;
        g_cur[side][i] = o;
    }
    if (i == 0) g_off[side][NNODES] = NEPLUS;
}

// ---------------- FUSED: edge scatter + layer-1 table gather ------------------------
__global__ void k_scat_l1(const int* __restrict__ el, const int* __restrict__ er,
                          const int* __restrict__ xl, const int* __restrict__ xr) {
    int t = threadIdx.x;
    if ((int)blockIdx.x < 2 * SCATBLK) {
        int side = blockIdx.x / SCATBLK;
        int e = (blockIdx.x - side * SCATBLK) * 256 + t;
        if (e < NEPLUS) {
            const int* edge = side ? er : el;
            int s, d;
            if (e < NEDGES) { s = edge[e]; d = edge[NEDGES + e]; }
            else            { s = d = e - NEDGES; }
            int p = atomicAdd(&g_cur[side][d], 1);
            g_srcs[side][p] = s;
        }
    } else {
        int j = (blockIdx.x - 2 * SCATBLK);
        int side = j / L1BLK;
        int idx = (j - side * L1BLK) * 256 + t;
        const int* xi = side ? xr : xl;
        int n = idx >> 7, q = idx & 127;
        int v = xi[n];
        float4 val = *(const float4*)(g_tab + v * 512 + q * 4);
        if (q < 64) {
            __half2 h0 = __floats2half2_rn(val.x, val.y);
            __half2 h1 = __floats2half2_rn(val.z, val.w);
            uint2 u = make_uint2(*(uint32_t*)&h0, *(uint32_t*)&h1);
            *(uint2*)(&g_xh[side][n * 256 + q * 4]) = u;
        } else {
            *(float4*)(&g_lin[side][n * 256 + (q - 64) * 4]) = val;
        }
        if (q == 0) {
            *(float4*)(&g_asb[0][side][n * 4]) = *(const float4*)(g_tatt + v * 8);
            *(float4*)(&g_adb[0][side][n * 4]) = *(const float4*)(g_tatt + v * 8 + 4);
        }
    }
}

// ---------------- fp16 GEMM with fused attention-score epilogue (per side) ----------
__device__ __forceinline__ void mma_f16(float* c, const unsigned* a, const unsigned* b) {
    asm volatile(
        "mma.sync.aligned.m16n8k16.row.col.f32.f16.f16.f32 "
        "{%0,%1,%2,%3},{%4,%5,%6,%7},{%8,%9},{%0,%1,%2,%3};"
        : "+f"(c[0]), "+f"(c[1]), "+f"(c[2]), "+f"(c[3])
        : "r"(a[0]), "r"(a[1]), "r"(a[2]), "r"(a[3]),
          "r"(b[0]), "r"(b[1]));
}

#define AS_STRIDE 40
#define BS_STRIDE 136
#define GEMM_SMEM ((2 * 128 * AS_STRIDE + 2 * 32 * BS_STRIDE) * 2)

__global__ __launch_bounds__(256) void k_gemm(
    int side, int layer,
    const __half* __restrict__ B1, int N1,
    const __half* __restrict__ B2, int N2,
    int K, const float* __restrict__ atts, const float* __restrict__ attd, int C) {
    extern __shared__ __half smh[];
    __half (*As)[128][AS_STRIDE] = (__half (*)[128][AS_STRIDE])smh;
    __half (*Bs)[32][BS_STRIDE] = (__half (*)[32][BS_STRIDE])(smh + 2 * 128 * AS_STRIDE);

    int bx = blockIdx.x, by = blockIdx.y;
    const int M = NNODES;
    const __half* A = g_feath[side];
    int t1 = N1 >> 7;
    bool ishalf = (bx < t1);
    const __half* B; int N, n0;
    __half* Ch = g_xh[side];
    float* Cf = g_lin[side];
    if (ishalf) { B = B1; N = N1; n0 = bx << 7; }
    else        { B = B2; N = N2; n0 = (bx - t1) << 7; }

    int tid = threadIdx.x;
    int warp = tid >> 5, lane = tid & 31;
    int m0 = by * 128;
    int wm = (warp >> 2) * 64;
    int wn = (warp & 3) * 32;
    int gid = lane >> 2, tig = lane & 3;

    float c[4][4][4];
#pragma unroll
    for (int i = 0; i < 4; i++)
#pragma unroll
        for (int j = 0; j < 4; j++)
#pragma unroll
            for (int r = 0; r < 4; r++) c[i][j][r] = 0.f;

    auto load_tile = [&](int s, int kk) {
#pragma unroll
        for (int i = 0; i < 2; i++) {
            int cid = tid + 256 * i;
            int row = cid >> 2, coff = (cid & 3) * 8;
            const __half* asrc = A + (size_t)(m0 + row) * K + kk + coff;
            int sz = (m0 + row < M) ? 16 : 0;
            if (!sz) asrc = A;
            CPA(sptr(&As[s][row][coff]), asrc, sz);
            int krow = cid >> 4, noff = (cid & 15) * 8;
            const __half* bsrc = B + (size_t)(kk + krow) * N + n0 + noff;
            CPA(sptr(&Bs[s][krow][noff]), bsrc, 16);
        }
        CP_COMMIT();
    };

    auto compute = [&](int s) {
#pragma unroll
        for (int ks = 0; ks < 2; ks++) {
            unsigned a[4][4], b[4][2];
#pragma unroll
            for (int mi = 0; mi < 4; mi++) {
                uint32_t addr = sptr(&As[s][wm + mi * 16 + (lane & 15)][ks * 16 + (lane >> 4) * 8]);
                asm volatile("ldmatrix.sync.aligned.m8n8.x4.shared.b16 {%0,%1,%2,%3}, [%4];"
                             : "=r"(a[mi][0]), "=r"(a[mi][1]), "=r"(a[mi][2]), "=r"(a[mi][3])
                             : "r"(addr));
            }
#pragma unroll
            for (int ni = 0; ni < 4; ni++) {
                uint32_t addr = sptr(&Bs[s][ks * 16 + (lane & 15)][wn + ni * 8]);
                asm volatile("ldmatrix.sync.aligned.m8n8.x2.trans.shared.b16 {%0,%1}, [%2];"
                             : "=r"(b[ni][0]), "=r"(b[ni][1])
                             : "r"(addr));
            }
#pragma unroll
            for (int mi = 0; mi < 4; mi++)
#pragma unroll
                for (int ni = 0; ni < 4; ni++) mma_f16(c[mi][ni], a[mi], b[ni]);
        }
    };

    int KT = K >> 5;
    load_tile(0, 0);
    for (int kt = 0; kt < KT; kt++) {
        if (kt + 1 < KT) {
            load_tile((kt + 1) & 1, (kt + 1) << 5);
            CP_WAIT1();
        } else {
            CP_WAIT0();
        }
        __syncthreads();
        compute(kt & 1);
        __syncthreads();
    }
#pragma unroll
    for (int mi = 0; mi < 4; mi++) {
#pragma unroll
        for (int ni = 0; ni < 4; ni++) {
            int r0 = m0 + wm + mi * 16 + gid;
            int cc = n0 + wn + ni * 8 + tig * 2;
            if (ishalf) {
                if (r0 < M)
                    *(__half2*)(Ch + (size_t)r0 * N + cc) =
                        __floats2half2_rn(c[mi][ni][0], c[mi][ni][1]);
                if (r0 + 8 < M)
                    *(__half2*)(Ch + (size_t)(r0 + 8) * N + cc) =
                        __floats2half2_rn(c[mi][ni][2], c[mi][ni][3]);
            } else {
                if (r0 < M)
                    *(float2*)(Cf + (size_t)r0 * N + cc) = make_float2(c[mi][ni][0], c[mi][ni][1]);
                if (r0 + 8 < M)
                    *(float2*)(Cf + (size_t)(r0 + 8) * N + cc) = make_float2(c[mi][ni][2], c[mi][ni][3]);
            }
        }
    }
    if (ishalf) {
        int h = (n0 + wn) / C;
        float av0[4], av1[4], bv0[4], bv1[4];
#pragma unroll
        for (int ni = 0; ni < 4; ni++) {
            int cc = n0 + wn + ni * 8 + tig * 2;
            av0[ni] = atts[cc]; av1[ni] = atts[cc + 1];
            bv0[ni] = attd[cc]; bv1[ni] = attd[cc + 1];
        }
        float* asb = g_asb[layer][side];
        float* adb = g_adb[layer][side];
#pragma unroll
        for (int mi = 0; mi < 4; mi++) {
            float s0 = 0.f, s1 = 0.f, d0 = 0.f, d1 = 0.f;
#pragma unroll
            for (int ni = 0; ni < 4; ni++) {
                s0 += c[mi][ni][0] * av0[ni] + c[mi][ni][1] * av1[ni];
                s1 += c[mi][ni][2] * av0[ni] + c[mi][ni][3] * av1[ni];
                d0 += c[mi][ni][0] * bv0[ni] + c[mi][ni][1] * bv1[ni];
                d1 += c[mi][ni][2] * bv0[ni] + c[mi][ni][3] * bv1[ni];
            }
#pragma unroll
            for (int o = 1; o <= 2; o <<= 1) {
                s0 += __shfl_xor_sync(0xffffffffu, s0, o);
                s1 += __shfl_xor_sync(0xffffffffu, s1, o);
                d0 += __shfl_xor_sync(0xffffffffu, d0, o);
                d1 += __shfl_xor_sync(0xffffffffu, d1, o);
            }
            if (tig == 0) {
                int r0 = m0 + wm + mi * 16 + gid;
                if (r0 < M) {
                    atomicAdd(&asb[r0 * 4 + h], s0);
                    atomicAdd(&adb[r0 * 4 + h], d0);
                }
                if (r0 + 8 < M) {
                    atomicAdd(&asb[(r0 + 8) * 4 + h], s1);
                    atomicAdd(&adb[(r0 + 8) * 4 + h], d1);
                }
            }
        }
    }
}

// ---------------- GAT kernels (per side, zero dynamic smem) ----------------
__global__ __launch_bounds__(256) void k_gat_concat(
    int side, int layer, const float* __restrict__ bias, const float* __restrict__ lbias,
    int relu_flag) {
    int i = blockIdx.x * 8 + (threadIdx.x >> 5);
    int lane = threadIdx.x & 31;
    if (i >= NNODES) return;
    int beg = g_off[side][i], end = g_off[side][i + 1];
    const float* asbuf = g_asb[layer][side];
    float4 ad = *(const float4*)(&g_adb[layer][side][(size_t)i * 4]);
    float z0 = 0.f, z1 = 0.f, z2 = 0.f, z3 = 0.f;
    for (int e = beg + lane; e < end; e += 32) {
        int s = g_srcs[side][e];
        float4 as = *(const float4*)(&asbuf[(size_t)s * 4]);
        float e0 = __expf(fminf(lrelu(as.x + ad.x), 80.f));
        float e1 = __expf(fminf(lrelu(as.y + ad.y), 80.f));
        float e2 = __expf(fminf(lrelu(as.z + ad.z), 80.f));
        float e3 = __expf(fminf(lrelu(as.w + ad.w), 80.f));
        *(float4*)(&g_exp[side][(size_t)e * 4]) = make_float4(e0, e1, e2, e3);
        z0 += e0; z1 += e1; z2 += e2; z3 += e3;
    }
    for (int o = 16; o; o >>= 1) {
        z0 += __shfl_xor_sync(0xffffffffu, z0, o);
        z1 += __shfl_xor_sync(0xffffffffu, z1, o);
        z2 += __shfl_xor_sync(0xffffffffu, z2, o);
        z3 += __shfl_xor_sync(0xffffffffu, z3, o);
    }
    float i0 = 1.f / (z0 + 1e-16f), i1 = 1.f / (z1 + 1e-16f);
    float i2 = 1.f / (z2 + 1e-16f), i3 = 1.f / (z3 + 1e-16f);
    int h = lane >> 3;
    float myinv = (h == 0) ? i0 : (h == 1) ? i1 : (h == 2) ? i2 : i3;
    int col = lane * 8;
    float a0 = 0.f, a1 = 0.f, a2 = 0.f, a3 = 0.f, a4 = 0.f, a5 = 0.f, a6 = 0.f, a7 = 0.f;
    for (int e = beg; e < end; e++) {
        int s = g_srcs[side][e];
        float w = g_exp[side][(size_t)e * 4 + h] * myinv;
        uint4 u = *(const uint4*)(g_xh[side] + (size_t)s * 256 + col);
        __half2* hp = (__half2*)&u;
        float2 f0 = __half22float2(hp[0]);
        float2 f1 = __half22float2(hp[1]);
        float2 f2 = __half22float2(hp[2]);
        float2 f3 = __half22float2(hp[3]);
        a0 += w * f0.x; a1 += w * f0.y; a2 += w * f1.x; a3 += w * f1.y;
        a4 += w * f2.x; a5 += w * f2.y; a6 += w * f3.x; a7 += w * f3.y;
    }
    float4 lr0 = *(const float4*)(g_lin[side] + (size_t)i * 256 + col);
    float4 lr1 = *(const float4*)(g_lin[side] + (size_t)i * 256 + col + 4);
    float4 b0 = *(const float4*)(bias + col);
    float4 b1 = *(const float4*)(bias + col + 4);
    float4 lb0 = *(const float4*)(lbias + col);
    float4 lb1 = *(const float4*)(lbias + col + 4);
    float o0x = a0 + b0.x + lr0.x + lb0.x, o0y = a1 + b0.y + lr0.y + lb0.y;
    float o0z = a2 + b0.z + lr0.z + lb0.z, o0w = a3 + b0.w + lr0.w + lb0.w;
    float o1x = a4 + b1.x + lr1.x + lb1.x, o1y = a5 + b1.y + lr1.y + lb1.y;
    float o1z = a6 + b1.z + lr1.z + lb1.z, o1w = a7 + b1.w + lr1.w + lb1.w;
    if (relu_flag) {
        o0x = fmaxf(o0x, 0.f); o0y = fmaxf(o0y, 0.f);
        o0z = fmaxf(o0z, 0.f); o0w = fmaxf(o0w, 0.f);
        o1x = fmaxf(o1x, 0.f); o1y = fmaxf(o1y, 0.f);
        o1z = fmaxf(o1z, 0.f); o1w = fmaxf(o1w, 0.f);
    }
    __half2 h0 = __floats2half2_rn(o0x, o0y);
    __half2 h1 = __floats2half2_rn(o0z, o0w);
    __half2 h2 = __floats2half2_rn(o1x, o1y);
    __half2 h3 = __floats2half2_rn(o1z, o1w);
    uint4 uo = make_uint4(*(uint32_t*)&h0, *(uint32_t*)&h1, *(uint32_t*)&h2, *(uint32_t*)&h3);
    *(uint4*)(&g_feath[side][(size_t)i * 256 + col]) = uo;
}

__global__ __launch_bounds__(256) void k_gat_mean(
    int side, const float* __restrict__ bias, const float* __restrict__ lbias) {
    int i = blockIdx.x * 8 + (threadIdx.x >> 5);
    int lane = threadIdx.x & 31;
    if (i >= NNODES) return;
    int beg = g_off[side][i], end = g_off[side][i + 1];
    const float* asbuf = g_asb[2][side];
    float4 ad = *(const float4*)(&g_adb[2][side][(size_t)i * 4]);
    float z0 = 0.f, z1 = 0.f, z2 = 0.f, z3 = 0.f;
    for (int e = beg + lane; e < end; e += 32) {
        int s = g_srcs[side][e];
        float4 as = *(const float4*)(&asbuf[(size_t)s * 4]);
        float e0 = __expf(fminf(lrelu(as.x + ad.x), 80.f));
        float e1 = __expf(fminf(lrelu(as.y + ad.y), 80.f));
        float e2 = __expf(fminf(lrelu(as.z + ad.z), 80.f));
        float e3 = __expf(fminf(lrelu(as.w + ad.w), 80.f));
        *(float4*)(&g_exp[side][(size_t)e * 4]) = make_float4(e0, e1, e2, e3);
        z0 += e0; z1 += e1; z2 += e2; z3 += e3;
    }
    for (int o = 16; o; o >>= 1) {
        z0 += __shfl_xor_sync(0xffffffffu, z0, o);
        z1 += __shfl_xor_sync(0xffffffffu, z1, o);
        z2 += __shfl_xor_sync(0xffffffffu, z2, o);
        z3 += __shfl_xor_sync(0xffffffffu, z3, o);
    }
    float i0 = 1.f / (z0 + 1e-16f), i1 = 1.f / (z1 + 1e-16f);
    float i2 = 1.f / (z2 + 1e-16f), i3 = 1.f / (z3 + 1e-16f);
    int h = lane >> 3;
    float myinv = (h == 0) ? i0 : (h == 1) ? i1 : (h == 2) ? i2 : i3;
    int col = lane * 16;
    float acc[16];
#pragma unroll
    for (int j = 0; j < 16; j++) acc[j] = 0.f;
    for (int e = beg; e < end; e++) {
        int s = g_srcs[side][e];
        float w = g_exp[side][(size_t)e * 4 + h] * myinv;
        const uint4* xr = (const uint4*)(g_xh[side] + (size_t)s * 512 + col);
        uint4 u0 = xr[0], u1 = xr[1];
        __half2* hp0 = (__half2*)&u0;
        __half2* hp1 = (__half2*)&u1;
#pragma unroll
        for (int j = 0; j < 4; j++) {
            float2 f = __half22float2(hp0[j]);
            acc[j * 2] += w * f.x; acc[j * 2 + 1] += w * f.y;
        }
#pragma unroll
        for (int j = 0; j < 4; j++) {
            float2 f = __half22float2(hp1[j]);
            acc[8 + j * 2] += w * f.x; acc[8 + j * 2 + 1] += w * f.y;
        }
    }
#pragma unroll
    for (int mask = 8; mask <= 16; mask <<= 1)
#pragma unroll
        for (int j = 0; j < 16; j++)
            acc[j] += __shfl_xor_sync(0xffffffffu, acc[j], mask);
    if (lane < 8) {
        int c0 = lane * 16;
#pragma unroll
        for (int j = 0; j < 4; j++) {
            int c = c0 + j * 4;
            float4 lr = *(const float4*)(g_lin[side] + (size_t)i * 128 + c);
            float4 bb = *(const float4*)(bias + c);
            float4 lb = *(const float4*)(lbias + c);
            float4 o;
            o.x = 0.25f * acc[j * 4 + 0] + bb.x + lr.x + lb.x;
            o.y = 0.25f * acc[j * 4 + 1] + bb.y + lr.y + lb.y;
            o.z = 0.25f * acc[j * 4 + 2] + bb.z + lr.z + lb.z;
            o.w = 0.25f * acc[j * 4 + 3] + bb.w + lr.w + lb.w;
            *(float4*)(g_feat[side] + (size_t)i * 128 + c) = o;
        }
    }
}

// ---------------- global mean pool (per side sum, joint div) ----------------
#define POOL_NB 64
__global__ void k_pool_sum(int side, const int* __restrict__ batch, float* out) {
    float* po = out + side * NGRAPH * 128;
    int n0 = blockIdx.x * POOL_NB;
    int c = threadIdx.x & 127;
    int r = threadIdx.x >> 7;
    float acc = 0.f;
    int cur = -1, cnt = 0;
    for (int j = r; j < POOL_NB; j += 2) {
        int n = n0 + j;
        if (n >= NNODES) break;
        int b = batch[n];
        if (b != cur) {
            if (cur >= 0) {
                atomicAdd(&po[cur * 128 + c], acc);
                if (c == 0) atomicAdd(&g_gcnt[side][cur], cnt);
            }
            acc = 0.f; cnt = 0; cur = b;
        }
        acc += g_feat[side][(size_t)n * 128 + c];
        cnt++;
    }
    if (cur >= 0) {
        atomicAdd(&po[cur * 128 + c], acc);
        if (c == 0) atomicAdd(&g_gcnt[side][cur], cnt);
    }
}
__global__ void k_pool_div(float* out) {
    int i = blockIdx.x * blockDim.x + threadIdx.x;
    if (i < 2 * NGRAPH * 128) {
        int side = i >> 15;
        float cnt = (float)g_gcnt[side][(i >> 7) & 255];
        out[i] /= fmaxf(cnt, 1.f);
    }
}

// ---------------- host orchestration: two-stream pipelined sides ----------------
extern "C" void kernel_launch(void* const* d_in, const int* in_sizes, int n_in,
                              void* d_out, int out_size) {
    const int* x_l     = (const int*)d_in[0];
    const int* edge_l  = (const int*)d_in[1];
    const int* batch_l = (const int*)d_in[2];
    const int* x_r     = (const int*)d_in[3];
    const int* edge_r  = (const int*)d_in[4];
    const int* batch_r = (const int*)d_in[5];
    const float* emb = (const float*)d_in[6];
    const float* W1  = (const float*)d_in[7];  const float* as1 = (const float*)d_in[8];
    const float* ad1 = (const float*)d_in[9];  const float* b1  = (const float*)d_in[10];
    const float* lw1 = (const float*)d_in[11]; const float* lb1 = (const float*)d_in[12];
    const float* W2  = (const float*)d_in[13]; const float* as2 = (const float*)d_in[14];
    const float* ad2 = (const float*)d_in[15]; const float* b2  = (const float*)d_in[16];
    const float* lw2 = (const float*)d_in[17]; const float* lb2 = (const float*)d_in[18];
    const float* W3  = (const float*)d_in[19]; const float* as3 = (const float*)d_in[20];
    const float* ad3 = (const float*)d_in[21]; const float* b3  = (const float*)d_in[22];
    const float* lw3 = (const float*)d_in[23]; const float* lb3 = (const float*)d_in[24];
    float* out = (float*)d_out;

    __half* wh;
    cudaGetSymbolAddress((void**)&wh, g_wh);

    cudaFuncSetAttribute(k_gemm, cudaFuncAttributeMaxDynamicSharedMemorySize, GEMM_SMEM);

    const int TB = 256;
    int init_grid = (2 * 2 * NNODES * 4 + TB - 1) / TB;
    if ((NWH + TB - 1) / TB > init_grid) init_grid = (NWH + TB - 1) / TB;

    // fork machinery (created per call; NOT destroyed — destruction mid-capture
    // would invalidate the graph; kernel_launch runs only twice on the host)
    cudaStream_t s1;
    cudaStreamCreateWithFlags(&s1, cudaStreamNonBlocking);
    cudaEvent_t evStag, evJoin;
    cudaEventCreateWithFlags(&evStag, cudaEventDisableTiming);
    cudaEventCreateWithFlags(&evJoin, cudaEventDisableTiming);

    // prologue (both sides) on origin stream
    k_init<<<init_grid, TB>>>(W2, lw2, W3, lw3, out);
    k_pre_hist<<<VOCAB + 2 * HISTBLK, TB>>>(emb, W1, lw1, as1, ad1, edge_l, edge_r);
    k_scan_a<<<dim3(79, 1, 2), 256>>>();
    k_scan_c<<<dim3(79, 1, 2), 256>>>();
    k_scat_l1<<<2 * SCATBLK + 2 * L1BLK, TB>>>(edge_l, edge_r, x_l, x_r);

    const __half *W2h = wh, *lw2h = wh + 65536, *W3h = wh + 131072, *lw3h = wh + 262144;
    dim3 gemm2(4, MBLK), gemm3(5, MBLK);

    // side L chain on origin stream; stagger event after gat1(L)
    k_gat_concat<<<GATBLK, TB>>>(0, 0, b1, lb1, 1);
    cudaEventRecord(evStag, 0);
    k_gemm<<<gemm2, 256, GEMM_SMEM>>>(0, 1, W2h, 256, lw2h, 256, 256, as2, ad2, 64);
    k_gat_concat<<<GATBLK, TB>>>(0, 1, b2, lb2, 1);
    k_gemm<<<gemm3, 256, GEMM_SMEM>>>(0, 2, W3h, 512, lw3h, 128, 256, as3, ad3, 128);
    k_gat_mean<<<GATBLK, TB>>>(0, b3, lb3);
    k_pool_sum<<<(NNODES + POOL_NB - 1) / POOL_NB, TB>>>(0, batch_l, out);

    // side R chain on forked stream, offset by one stage
    cudaStreamWaitEvent(s1, evStag, 0);
    k_gat_concat<<<GATBLK, TB, 0, s1>>>(1, 0, b1, lb1, 1);
    k_gemm<<<gemm2, 256, GEMM_SMEM, s1>>>(1, 1, W2h, 256, lw2h, 256, 256, as2, ad2, 64);
    k_gat_concat<<<GATBLK, TB, 0, s1>>>(1, 1, b2, lb2, 1);
    k_gemm<<<gemm3, 256, GEMM_SMEM, s1>>>(1, 2, W3h, 512, lw3h, 128, 256, as3, ad3, 128);
    k_gat_mean<<<GATBLK, TB, 0, s1>>>(1, b3, lb3);
    k_pool_sum<<<(NNODES + POOL_NB - 1) / POOL_NB, TB, 0, s1>>>(1, batch_r, out);
    cudaEventRecord(evJoin, s1);

    // rejoin and finish on origin stream
    cudaStreamWaitEvent(0, evJoin, 0);
    k_pool_div<<<(2 * NGRAPH * 128 + TB - 1) / TB, TB>>>(out);
}

// round 16
// speedup vs baseline: 1.2869x; 1.0114x over previous
#include <cuda_runtime.h>
#include <cuda_fp16.h>
#include <cstdint>

#define NNODES 20000
#define NEDGES 320000
#define NEPLUS 340000   // edges + self loops
#define NGRAPH 256
#define VOCAB  128
#define NWH    294912   // fp16 weights: W2(65536) lw2(65536) W3(131072) lw3(32768)
#define MBLK   157      // ceil(20000/128)
#define GATBLK 2500     // ceil(20000/8)
#define HISTBLK 1250    // ceil(NEDGES/256)
#define SCATBLK 1329    // ceil(NEPLUS/256)
#define L1BLK   10000   // NNODES*128/256

// ---------------- scratch (device globals; no runtime alloc allowed) ----------------
__device__ float  g_feat [2][NNODES * 128];
__device__ __half g_feath[2][NNODES * 256];
__device__ __half g_xh   [2][NNODES * 512];
__device__ float  g_lin  [2][NNODES * 256];
__device__ float  g_asb  [3][2][NNODES * 4];
__device__ float  g_adb  [3][2][NNODES * 4];
__device__ int    g_off  [2][NNODES + 1];
__device__ int    g_cur  [2][NNODES];
__device__ int    g_srcs [2][NEPLUS];
__device__ int    g_gcnt [2][NGRAPH];
__device__ int    g_bsum [2][128];
__device__ float  g_tab  [VOCAB * 512];
__device__ float  g_tatt [VOCAB * 8];
__device__ __half g_wh   [NWH];

__device__ __forceinline__ float lrelu(float x) { return x > 0.f ? x : 0.2f * x; }

__device__ __forceinline__ uint32_t sptr(const void* p) {
    return (uint32_t)__cvta_generic_to_shared(p);
}
#define CPA(dst, src, sz) \
    asm volatile("cp.async.cg.shared.global [%0], [%1], 16, %2;" :: "r"(dst), "l"(src), "r"(sz))
#define CP_COMMIT() asm volatile("cp.async.commit_group;" ::: "memory")
#define CP_WAIT1()  asm volatile("cp.async.wait_group 1;" ::: "memory")
#define CP_WAIT0()  asm volatile("cp.async.wait_group 0;" ::: "memory")

// ---------------- init A (main stream): CSR counts, pool, out ----------------
__global__ void k_init_csr(float* out) {
    int i = blockIdx.x * blockDim.x + threadIdx.x;
    if (i < 2 * NNODES) g_cur[i / NNODES][i % NNODES] = 1;
    if (i < 2 * NGRAPH * 128) out[i] = 0.f;
    if (i < 2 * NGRAPH) g_gcnt[i >> 8][i & 255] = 0;
}

// ---------------- init B (side stream): weight fp16 conversion + score zero ---------
__global__ void k_wconv_zero(const float* __restrict__ W2, const float* __restrict__ lw2,
                             const float* __restrict__ W3, const float* __restrict__ lw3) {
    int i = blockIdx.x * blockDim.x + threadIdx.x;
    if (i < NWH) {
        float v;
        if (i < 65536)       v = W2[i];
        else if (i < 131072) v = lw2[i - 65536];
        else if (i < 262144) v = W3[i - 131072];
        else                 v = lw3[i - 262144];
        g_wh[i] = __float2half_rn(v);
    }
    if (i < 2 * 2 * NNODES * 4) {
        int l = 1 + i / (2 * NNODES * 4);
        int r = i % (2 * NNODES * 4);
        g_asb[l][r / (NNODES * 4)][r % (NNODES * 4)] = 0.f;
        g_adb[l][r / (NNODES * 4)][r % (NNODES * 4)] = 0.f;
    }
}

// ---------------- FUSED: layer-1 table precompute + edge histogram ------------------
__global__ void k_pre_hist(const float* __restrict__ emb, const float* __restrict__ W1,
                           const float* __restrict__ lw1, const float* __restrict__ as1,
                           const float* __restrict__ ad1,
                           const int* __restrict__ el, const int* __restrict__ er) {
    __shared__ float er_s[128];
    __shared__ float sAs[4], sAd[4];
    int t = threadIdx.x;
    if ((int)blockIdx.x < VOCAB) {
        int v = blockIdx.x;
        if (t < 128) er_s[t] = emb[v * 128 + t];
        if (t < 4) { sAs[t] = 0.f; sAd[t] = 0.f; }
        __syncthreads();
        float acc0 = 0.f, acc1 = 0.f;
        for (int k = 0; k < 128; k++) {
            float e = er_s[k];
            acc0 += e * W1[k * 256 + t];
            acc1 += e * lw1[k * 256 + t];
        }
        g_tab[v * 512 + t] = acc0;
        g_tab[v * 512 + 256 + t] = acc1;
        int h = t >> 6, c = t & 63;
        atomicAdd(&sAs[h], acc0 * as1[h * 64 + c]);
        atomicAdd(&sAd[h], acc0 * ad1[h * 64 + c]);
        __syncthreads();
        if (t < 4) { g_tatt[v * 8 + t] = sAs[t]; g_tatt[v * 8 + 4 + t] = sAd[t]; }
    } else {
        int j = (blockIdx.x - VOCAB) * 256 + t;
        if (j < 2 * NEDGES) {
            int side = j / NEDGES;
            int e = j - side * NEDGES;
            const int* edge = side ? er : el;
            atomicAdd(&g_cur[side][edge[NEDGES + e]], 1);
        }
    }
}

// ---------------- scan ----------------
__global__ void k_scan_a() {
    int side = blockIdx.z;
    __shared__ int sh[256];
    int t = threadIdx.x, i = blockIdx.x * 256 + t;
    int v = (i < NNODES) ? g_cur[side][i] : 0;
    sh[t] = v;
    __syncthreads();
    for (int o = 1; o < 256; o <<= 1) {
        int x = (t >= o) ? sh[t - o] : 0;
        __syncthreads();
        sh[t] += x;
        __syncthreads();
    }
    if (i < NNODES) g_off[side][i] = sh[t] - v;
    if (t == 255) g_bsum[side][blockIdx.x] = sh[255];
}
__global__ void k_scan_c() {
    int side = blockIdx.z;
    int bx = blockIdx.x, t = threadIdx.x;
    __shared__ int sbase;
    if (t < 32) {
        int s = 0;
        for (int j = t; j < 79; j += 32)
            if (j < bx) s += g_bsum[side][j];
        for (int o = 16; o; o >>= 1) s += __shfl_xor_sync(0xffffffffu, s, o);
        if (t == 0) sbase = s;
    }
    __syncthreads();
    int base = sbase;
    int i = bx * 256 + t;
    if (i < NNODES) {
        int o = g_off[side][i] + base;
        g_off[side][i] = o;
        g_cur[side][i] = o;
    }
    if (i == 0) g_off[side][NNODES] = NEPLUS;
}

// ---------------- FUSED: edge scatter + layer-1 table gather ------------------------
__global__ void k_scat_l1(const int* __restrict__ el, const int* __restrict__ er,
                          const int* __restrict__ xl, const int* __restrict__ xr) {
    int t = threadIdx.x;
    if ((int)blockIdx.x < 2 * SCATBLK) {
        int side = blockIdx.x / SCATBLK;
        int e = (blockIdx.x - side * SCATBLK) * 256 + t;
        if (e < NEPLUS) {
            const int* edge = side ? er : el;
            int s, d;
            if (e < NEDGES) { s = edge[e]; d = edge[NEDGES + e]; }
            else            { s = d = e - NEDGES; }
            int p = atomicAdd(&g_cur[side][d], 1);
            g_srcs[side][p] = s;
        }
    } else {
        int j = (blockIdx.x - 2 * SCATBLK);
        int side = j / L1BLK;
        int idx = (j - side * L1BLK) * 256 + t;
        const int* xi = side ? xr : xl;
        int n = idx >> 7, q = idx & 127;
        int v = xi[n];
        float4 val = *(const float4*)(g_tab + v * 512 + q * 4);
        if (q < 64) {
            __half2 h0 = __floats2half2_rn(val.x, val.y);
            __half2 h1 = __floats2half2_rn(val.z, val.w);
            uint2 u = make_uint2(*(uint32_t*)&h0, *(uint32_t*)&h1);
            *(uint2*)(&g_xh[side][n * 256 + q * 4]) = u;
        } else {
            *(float4*)(&g_lin[side][n * 256 + (q - 64) * 4]) = val;
        }
        if (q == 0) {
            *(float4*)(&g_asb[0][side][n * 4]) = *(const float4*)(g_tatt + v * 8);
            *(float4*)(&g_adb[0][side][n * 4]) = *(const float4*)(g_tatt + v * 8 + 4);
        }
    }
}

// ---------------- fp16 GEMM with fused attention-score epilogue (per side) ----------
__device__ __forceinline__ void mma_f16(float* c, const unsigned* a, const unsigned* b) {
    asm volatile(
        "mma.sync.aligned.m16n8k16.row.col.f32.f16.f16.f32 "
        "{%0,%1,%2,%3},{%4,%5,%6,%7},{%8,%9},{%0,%1,%2,%3};"
        : "+f"(c[0]), "+f"(c[1]), "+f"(c[2]), "+f"(c[3])
        : "r"(a[0]), "r"(a[1]), "r"(a[2]), "r"(a[3]),
          "r"(b[0]), "r"(b[1]));
}

#define AS_STRIDE 40
#define BS_STRIDE 136
#define GEMM_SMEM ((2 * 128 * AS_STRIDE + 2 * 32 * BS_STRIDE) * 2)

__global__ __launch_bounds__(256) void k_gemm(
    int side, int layer,
    const __half* __restrict__ B1, int N1,
    const __half* __restrict__ B2, int N2,
    int K, const float* __restrict__ atts, const float* __restrict__ attd, int C) {
    extern __shared__ __half smh[];
    __half (*As)[128][AS_STRIDE] = (__half (*)[128][AS_STRIDE])smh;
    __half (*Bs)[32][BS_STRIDE] = (__half (*)[32][BS_STRIDE])(smh + 2 * 128 * AS_STRIDE);

    int bx = blockIdx.x, by = blockIdx.y;
    const int M = NNODES;
    const __half* A = g_feath[side];
    int t1 = N1 >> 7;
    bool ishalf = (bx < t1);
    const __half* B; int N, n0;
    __half* Ch = g_xh[side];
    float* Cf = g_lin[side];
    if (ishalf) { B = B1; N = N1; n0 = bx << 7; }
    else        { B = B2; N = N2; n0 = (bx - t1) << 7; }

    int tid = threadIdx.x;
    int warp = tid >> 5, lane = tid & 31;
    int m0 = by * 128;
    int wm = (warp >> 2) * 64;
    int wn = (warp & 3) * 32;
    int gid = lane >> 2, tig = lane & 3;

    float c[4][4][4];
#pragma unroll
    for (int i = 0; i < 4; i++)
#pragma unroll
        for (int j = 0; j < 4; j++)
#pragma unroll
            for (int r = 0; r < 4; r++) c[i][j][r] = 0.f;

    auto load_tile = [&](int s, int kk) {
#pragma unroll
        for (int i = 0; i < 2; i++) {
            int cid = tid + 256 * i;
            int row = cid >> 2, coff = (cid & 3) * 8;
            const __half* asrc = A + (size_t)(m0 + row) * K + kk + coff;
            int sz = (m0 + row < M) ? 16 : 0;
            if (!sz) asrc = A;
            CPA(sptr(&As[s][row][coff]), asrc, sz);
            int krow = cid >> 4, noff = (cid & 15) * 8;
            const __half* bsrc = B + (size_t)(kk + krow) * N + n0 + noff;
            CPA(sptr(&Bs[s][krow][noff]), bsrc, 16);
        }
        CP_COMMIT();
    };

    auto compute = [&](int s) {
#pragma unroll
        for (int ks = 0; ks < 2; ks++) {
            unsigned a[4][4], b[4][2];
#pragma unroll
            for (int mi = 0; mi < 4; mi++) {
                uint32_t addr = sptr(&As[s][wm + mi * 16 + (lane & 15)][ks * 16 + (lane >> 4) * 8]);
                asm volatile("ldmatrix.sync.aligned.m8n8.x4.shared.b16 {%0,%1,%2,%3}, [%4];"
                             : "=r"(a[mi][0]), "=r"(a[mi][1]), "=r"(a[mi][2]), "=r"(a[mi][3])
                             : "r"(addr));
            }
#pragma unroll
            for (int ni = 0; ni < 4; ni++) {
                uint32_t addr = sptr(&Bs[s][ks * 16 + (lane & 15)][wn + ni * 8]);
                asm volatile("ldmatrix.sync.aligned.m8n8.x2.trans.shared.b16 {%0,%1}, [%2];"
                             : "=r"(b[ni][0]), "=r"(b[ni][1])
                             : "r"(addr));
            }
#pragma unroll
            for (int mi = 0; mi < 4; mi++)
#pragma unroll
                for (int ni = 0; ni < 4; ni++) mma_f16(c[mi][ni], a[mi], b[ni]);
        }
    };

    int KT = K >> 5;
    load_tile(0, 0);
    for (int kt = 0; kt < KT; kt++) {
        if (kt + 1 < KT) {
            load_tile((kt + 1) & 1, (kt + 1) << 5);
            CP_WAIT1();
        } else {
            CP_WAIT0();
        }
        __syncthreads();
        compute(kt & 1);
        __syncthreads();
    }
#pragma unroll
    for (int mi = 0; mi < 4; mi++) {
#pragma unroll
        for (int ni = 0; ni < 4; ni++) {
            int r0 = m0 + wm + mi * 16 + gid;
            int cc = n0 + wn + ni * 8 + tig * 2;
            if (ishalf) {
                if (r0 < M)
                    *(__half2*)(Ch + (size_t)r0 * N + cc) =
                        __floats2half2_rn(c[mi][ni][0], c[mi][ni][1]);
                if (r0 + 8 < M)
                    *(__half2*)(Ch + (size_t)(r0 + 8) * N + cc) =
                        __floats2half2_rn(c[mi][ni][2], c[mi][ni][3]);
            } else {
                if (r0 < M)
                    *(float2*)(Cf + (size_t)r0 * N + cc) = make_float2(c[mi][ni][0], c[mi][ni][1]);
                if (r0 + 8 < M)
                    *(float2*)(Cf + (size_t)(r0 + 8) * N + cc) = make_float2(c[mi][ni][2], c[mi][ni][3]);
            }
        }
    }
    if (ishalf) {
        int h = (n0 + wn) / C;
        float av0[4], av1[4], bv0[4], bv1[4];
#pragma unroll
        for (int ni = 0; ni < 4; ni++) {
            int cc = n0 + wn + ni * 8 + tig * 2;
            av0[ni] = atts[cc]; av1[ni] = atts[cc + 1];
            bv0[ni] = attd[cc]; bv1[ni] = attd[cc + 1];
        }
        float* asb = g_asb[layer][side];
        float* adb = g_adb[layer][side];
#pragma unroll
        for (int mi = 0; mi < 4; mi++) {
            float s0 = 0.f, s1 = 0.f, d0 = 0.f, d1 = 0.f;
#pragma unroll
            for (int ni = 0; ni < 4; ni++) {
                s0 += c[mi][ni][0] * av0[ni] + c[mi][ni][1] * av1[ni];
                s1 += c[mi][ni][2] * av0[ni] + c[mi][ni][3] * av1[ni];
                d0 += c[mi][ni][0] * bv0[ni] + c[mi][ni][1] * bv1[ni];
                d1 += c[mi][ni][2] * bv0[ni] + c[mi][ni][3] * bv1[ni];
            }
#pragma unroll
            for (int o = 1; o <= 2; o <<= 1) {
                s0 += __shfl_xor_sync(0xffffffffu, s0, o);
                s1 += __shfl_xor_sync(0xffffffffu, s1, o);
                d0 += __shfl_xor_sync(0xffffffffu, d0, o);
                d1 += __shfl_xor_sync(0xffffffffu, d1, o);
            }
            if (tig == 0) {
                int r0 = m0 + wm + mi * 16 + gid;
                if (r0 < M) {
                    atomicAdd(&asb[r0 * 4 + h], s0);
                    atomicAdd(&adb[r0 * 4 + h], d0);
                }
                if (r0 + 8 < M) {
                    atomicAdd(&asb[(r0 + 8) * 4 + h], s1);
                    atomicAdd(&adb[(r0 + 8) * 4 + h], d1);
                }
            }
        }
    }
}

// ---------------- GAT kernels: pass A computes z only; pass B recomputes w ----------
__global__ __launch_bounds__(256) void k_gat_concat(
    int side, int layer, const float* __restrict__ bias, const float* __restrict__ lbias,
    int relu_flag) {
    int i = blockIdx.x * 8 + (threadIdx.x >> 5);
    int lane = threadIdx.x & 31;
    if (i >= NNODES) return;
    int beg = g_off[side][i], end = g_off[side][i + 1];
    const float* asbuf = g_asb[layer][side];
    float4 ad = *(const float4*)(&g_adb[layer][side][(size_t)i * 4]);
    float z0 = 0.f, z1 = 0.f, z2 = 0.f, z3 = 0.f;
    for (int e = beg + lane; e < end; e += 32) {
        int s = g_srcs[side][e];
        float4 as = *(const float4*)(&asbuf[(size_t)s * 4]);
        z0 += __expf(fminf(lrelu(as.x + ad.x), 80.f));
        z1 += __expf(fminf(lrelu(as.y + ad.y), 80.f));
        z2 += __expf(fminf(lrelu(as.z + ad.z), 80.f));
        z3 += __expf(fminf(lrelu(as.w + ad.w), 80.f));
    }
    for (int o = 16; o; o >>= 1) {
        z0 += __shfl_xor_sync(0xffffffffu, z0, o);
        z1 += __shfl_xor_sync(0xffffffffu, z1, o);
        z2 += __shfl_xor_sync(0xffffffffu, z2, o);
        z3 += __shfl_xor_sync(0xffffffffu, z3, o);
    }
    float i0 = 1.f / (z0 + 1e-16f), i1 = 1.f / (z1 + 1e-16f);
    float i2 = 1.f / (z2 + 1e-16f), i3 = 1.f / (z3 + 1e-16f);
    int h = lane >> 3;
    float myinv = (h == 0) ? i0 : (h == 1) ? i1 : (h == 2) ? i2 : i3;
    float adh = (h == 0) ? ad.x : (h == 1) ? ad.y : (h == 2) ? ad.z : ad.w;
    int col = lane * 8;
    float a0 = 0.f, a1 = 0.f, a2 = 0.f, a3 = 0.f, a4 = 0.f, a5 = 0.f, a6 = 0.f, a7 = 0.f;
    for (int e = beg; e < end; e++) {
        int s = g_srcs[side][e];
        float ash = asbuf[(size_t)s * 4 + h];
        float w = __expf(fminf(lrelu(ash + adh), 80.f)) * myinv;
        uint4 u = *(const uint4*)(g_xh[side] + (size_t)s * 256 + col);
        __half2* hp = (__half2*)&u;
        float2 f0 = __half22float2(hp[0]);
        float2 f1 = __half22float2(hp[1]);
        float2 f2 = __half22float2(hp[2]);
        float2 f3 = __half22float2(hp[3]);
        a0 += w * f0.x; a1 += w * f0.y; a2 += w * f1.x; a3 += w * f1.y;
        a4 += w * f2.x; a5 += w * f2.y; a6 += w * f3.x; a7 += w * f3.y;
    }
    float4 lr0 = *(const float4*)(g_lin[side] + (size_t)i * 256 + col);
    float4 lr1 = *(const float4*)(g_lin[side] + (size_t)i * 256 + col + 4);
    float4 b0 = *(const float4*)(bias + col);
    float4 b1 = *(const float4*)(bias + col + 4);
    float4 lb0 = *(const float4*)(lbias + col);
    float4 lb1 = *(const float4*)(lbias + col + 4);
    float o0x = a0 + b0.x + lr0.x + lb0.x, o0y = a1 + b0.y + lr0.y + lb0.y;
    float o0z = a2 + b0.z + lr0.z + lb0.z, o0w = a3 + b0.w + lr0.w + lb0.w;
    float o1x = a4 + b1.x + lr1.x + lb1.x, o1y = a5 + b1.y + lr1.y + lb1.y;
    float o1z = a6 + b1.z + lr1.z + lb1.z, o1w = a7 + b1.w + lr1.w + lb1.w;
    if (relu_flag) {
        o0x = fmaxf(o0x, 0.f); o0y = fmaxf(o0y, 0.f);
        o0z = fmaxf(o0z, 0.f); o0w = fmaxf(o0w, 0.f);
        o1x = fmaxf(o1x, 0.f); o1y = fmaxf(o1y, 0.f);
        o1z = fmaxf(o1z, 0.f); o1w = fmaxf(o1w, 0.f);
    }
    __half2 h0 = __floats2half2_rn(o0x, o0y);
    __half2 h1 = __floats2half2_rn(o0z, o0w);
    __half2 h2 = __floats2half2_rn(o1x, o1y);
    __half2 h3 = __floats2half2_rn(o1z, o1w);
    uint4 uo = make_uint4(*(uint32_t*)&h0, *(uint32_t*)&h1, *(uint32_t*)&h2, *(uint32_t*)&h3);
    *(uint4*)(&g_feath[side][(size_t)i * 256 + col]) = uo;
}

__global__ __launch_bounds__(256) void k_gat_mean(
    int side, const float* __restrict__ bias, const float* __restrict__ lbias) {
    int i = blockIdx.x * 8 + (threadIdx.x >> 5);
    int lane = threadIdx.x & 31;
    if (i >= NNODES) return;
    int beg = g_off[side][i], end = g_off[side][i + 1];
    const float* asbuf = g_asb[2][side];
    float4 ad = *(const float4*)(&g_adb[2][side][(size_t)i * 4]);
    float z0 = 0.f, z1 = 0.f, z2 = 0.f, z3 = 0.f;
    for (int e = beg + lane; e < end; e += 32) {
        int s = g_srcs[side][e];
        float4 as = *(const float4*)(&asbuf[(size_t)s * 4]);
        z0 += __expf(fminf(lrelu(as.x + ad.x), 80.f));
        z1 += __expf(fminf(lrelu(as.y + ad.y), 80.f));
        z2 += __expf(fminf(lrelu(as.z + ad.z), 80.f));
        z3 += __expf(fminf(lrelu(as.w + ad.w), 80.f));
    }
    for (int o = 16; o; o >>= 1) {
        z0 += __shfl_xor_sync(0xffffffffu, z0, o);
        z1 += __shfl_xor_sync(0xffffffffu, z1, o);
        z2 += __shfl_xor_sync(0xffffffffu, z2, o);
        z3 += __shfl_xor_sync(0xffffffffu, z3, o);
    }
    float i0 = 1.f / (z0 + 1e-16f), i1 = 1.f / (z1 + 1e-16f);
    float i2 = 1.f / (z2 + 1e-16f), i3 = 1.f / (z3 + 1e-16f);
    int h = lane >> 3;
    float myinv = (h == 0) ? i0 : (h == 1) ? i1 : (h == 2) ? i2 : i3;
    float adh = (h == 0) ? ad.x : (h == 1) ? ad.y : (h == 2) ? ad.z : ad.w;
    int col = lane * 16;
    float acc[16];
#pragma unroll
    for (int j = 0; j < 16; j++) acc[j] = 0.f;
    for (int e = beg; e < end; e++) {
        int s = g_srcs[side][e];
        float ash = asbuf[(size_t)s * 4 + h];
        float w = __expf(fminf(lrelu(ash + adh), 80.f)) * myinv;
        const uint4* xr = (const uint4*)(g_xh[side] + (size_t)s * 512 + col);
        uint4 u0 = xr[0], u1 = xr[1];
        __half2* hp0 = (__half2*)&u0;
        __half2* hp1 = (__half2*)&u1;
#pragma unroll
        for (int j = 0; j < 4; j++) {
            float2 f = __half22float2(hp0[j]);
            acc[j * 2] += w * f.x; acc[j * 2 + 1] += w * f.y;
        }
#pragma unroll
        for (int j = 0; j < 4; j++) {
            float2 f = __half22float2(hp1[j]);
            acc[8 + j * 2] += w * f.x; acc[8 + j * 2 + 1] += w * f.y;
        }
    }
#pragma unroll
    for (int mask = 8; mask <= 16; mask <<= 1)
#pragma unroll
        for (int j = 0; j < 16; j++)
            acc[j] += __shfl_xor_sync(0xffffffffu, acc[j], mask);
    if (lane < 8) {
        int c0 = lane * 16;
#pragma unroll
        for (int j = 0; j < 4; j++) {
            int c = c0 + j * 4;
            float4 lr = *(const float4*)(g_lin[side] + (size_t)i * 128 + c);
            float4 bb = *(const float4*)(bias + c);
            float4 lb = *(const float4*)(lbias + c);
            float4 o;
            o.x = 0.25f * acc[j * 4 + 0] + bb.x + lr.x + lb.x;
            o.y = 0.25f * acc[j * 4 + 1] + bb.y + lr.y + lb.y;
            o.z = 0.25f * acc[j * 4 + 2] + bb.z + lr.z + lb.z;
            o.w = 0.25f * acc[j * 4 + 3] + bb.w + lr.w + lb.w;
            *(float4*)(g_feat[side] + (size_t)i * 128 + c) = o;
        }
    }
}

// ---------------- global mean pool ----------------
#define POOL_NB 64
__global__ void k_pool_sum(int side, const int* __restrict__ batch, float* out) {
    float* po = out + side * NGRAPH * 128;
    int n0 = blockIdx.x * POOL_NB;
    int c = threadIdx.x & 127;
    int r = threadIdx.x >> 7;
    float acc = 0.f;
    int cur = -1, cnt = 0;
    for (int j = r; j < POOL_NB; j += 2) {
        int n = n0 + j;
        if (n >= NNODES) break;
        int b = batch[n];
        if (b != cur) {
            if (cur >= 0) {
                atomicAdd(&po[cur * 128 + c], acc);
                if (c == 0) atomicAdd(&g_gcnt[side][cur], cnt);
            }
            acc = 0.f; cnt = 0; cur = b;
        }
        acc += g_feat[side][(size_t)n * 128 + c];
        cnt++;
    }
    if (cur >= 0) {
        atomicAdd(&po[cur * 128 + c], acc);
        if (c == 0) atomicAdd(&g_gcnt[side][cur], cnt);
    }
}
__global__ void k_pool_div(float* out) {
    int i = blockIdx.x * blockDim.x + threadIdx.x;
    if (i < 2 * NGRAPH * 128) {
        int side = i >> 15;
        float cnt = (float)g_gcnt[side][(i >> 7) & 255];
        out[i] /= fmaxf(cnt, 1.f);
    }
}

// ---------------- host orchestration: two-stream pipelined sides ----------------
extern "C" void kernel_launch(void* const* d_in, const int* in_sizes, int n_in,
                              void* d_out, int out_size) {
    const int* x_l     = (const int*)d_in[0];
    const int* edge_l  = (const int*)d_in[1];
    const int* batch_l = (const int*)d_in[2];
    const int* x_r     = (const int*)d_in[3];
    const int* edge_r  = (const int*)d_in[4];
    const int* batch_r = (const int*)d_in[5];
    const float* emb = (const float*)d_in[6];
    const float* W1  = (const float*)d_in[7];  const float* as1 = (const float*)d_in[8];
    const float* ad1 = (const float*)d_in[9];  const float* b1  = (const float*)d_in[10];
    const float* lw1 = (const float*)d_in[11]; const float* lb1 = (const float*)d_in[12];
    const float* W2  = (const float*)d_in[13]; const float* as2 = (const float*)d_in[14];
    const float* ad2 = (const float*)d_in[15]; const float* b2  = (const float*)d_in[16];
    const float* lw2 = (const float*)d_in[17]; const float* lb2 = (const float*)d_in[18];
    const float* W3  = (const float*)d_in[19]; const float* as3 = (const float*)d_in[20];
    const float* ad3 = (const float*)d_in[21]; const float* b3  = (const float*)d_in[22];
    const float* lw3 = (const float*)d_in[23]; const float* lb3 = (const float*)d_in[24];
    float* out = (float*)d_out;

    __half* wh;
    cudaGetSymbolAddress((void**)&wh, g_wh);

    cudaFuncSetAttribute(k_gemm, cudaFuncAttributeMaxDynamicSharedMemorySize, GEMM_SMEM);

    const int TB = 256;
    int wz_grid = (2 * 2 * NNODES * 4 + TB - 1) / TB;
    if ((NWH + TB - 1) / TB > wz_grid) wz_grid = (NWH + TB - 1) / TB;

    // fork machinery (created per call; not destroyed — kernel_launch runs twice on host)
    cudaStream_t s1;
    cudaStreamCreateWithFlags(&s1, cudaStreamNonBlocking);
    cudaEvent_t evFork, evW, evStag, evJoin;
    cudaEventCreateWithFlags(&evFork, cudaEventDisableTiming);
    cudaEventCreateWithFlags(&evW, cudaEventDisableTiming);
    cudaEventCreateWithFlags(&evStag, cudaEventDisableTiming);
    cudaEventCreateWithFlags(&evJoin, cudaEventDisableTiming);

    // main: CSR-critical init; s1: weight conversion + score zeroing (independent)
    k_init_csr<<<(2 * NGRAPH * 128 + TB - 1) / TB, TB>>>(out);
    cudaEventRecord(evFork, 0);
    cudaStreamWaitEvent(s1, evFork, 0);
    k_wconv_zero<<<wz_grid, TB, 0, s1>>>(W2, lw2, W3, lw3);
    cudaEventRecord(evW, s1);

    // main: CSR chain (overlaps wconv)
    k_pre_hist<<<VOCAB + 2 * HISTBLK, TB>>>(emb, W1, lw1, as1, ad1, edge_l, edge_r);
    k_scan_a<<<dim3(79, 1, 2), 256>>>();
    k_scan_c<<<dim3(79, 1, 2), 256>>>();
    k_scat_l1<<<2 * SCATBLK + 2 * L1BLK, TB>>>(edge_l, edge_r, x_l, x_r);

    const __half *W2h = wh, *lw2h = wh + 65536, *W3h = wh + 131072, *lw3h = wh + 262144;
    dim3 gemm2(4, MBLK), gemm3(5, MBLK);

    // side L chain (main stream); must see converted weights before gemm2
    k_gat_concat<<<GATBLK, TB>>>(0, 0, b1, lb1, 1);
    cudaEventRecord(evStag, 0);
    cudaStreamWaitEvent(0, evW, 0);
    k_gemm<<<gemm2, 256, GEMM_SMEM>>>(0, 1, W2h, 256, lw2h, 256, 256, as2, ad2, 64);
    k_gat_concat<<<GATBLK, TB>>>(0, 1, b2, lb2, 1);
    k_gemm<<<gemm3, 256, GEMM_SMEM>>>(0, 2, W3h, 512, lw3h, 128, 256, as3, ad3, 128);
    k_gat_mean<<<GATBLK, TB>>>(0, b3, lb3);
    k_pool_sum<<<(NNODES + POOL_NB - 1) / POOL_NB, TB>>>(0, batch_l, out);

    // side R chain (s1), offset by one stage; wconv already sequenced on s1
    cudaStreamWaitEvent(s1, evStag, 0);
    k_gat_concat<<<GATBLK, TB, 0, s1>>>(1, 0, b1, lb1, 1);
    k_gemm<<<gemm2, 256, GEMM_SMEM, s1>>>(1, 1, W2h, 256, lw2h, 256, 256, as2, ad2, 64);
    k_gat_concat<<<GATBLK, TB, 0, s1>>>(1, 1, b2, lb2, 1);
    k_gemm<<<gemm3, 256, GEMM_SMEM, s1>>>(1, 2, W3h, 512, lw3h, 128, 256, as3, ad3, 128);
    k_gat_mean<<<GATBLK, TB, 0, s1>>>(1, b3, lb3);
    k_pool_sum<<<(NNODES + POOL_NB - 1) / POOL_NB, TB, 0, s1>>>(1, batch_r, out);
    cudaEventRecord(evJoin, s1);

    // rejoin and finish
    cudaStreamWaitEvent(0, evJoin, 0);
    k_pool_div<<<(2 * NGRAPH * 128 + TB - 1) / TB, TB>>>(out);
}

// round 17
// speedup vs baseline: 1.3445x; 1.0447x over previous
#include <cuda_runtime.h>
#include <cuda_fp16.h>
#include <cstdint>

#define NNODES 20000
#define NEDGES 320000
#define NEPLUS 340000   // edges + self loops
#define NGRAPH 256
#define VOCAB  128
#define NWH    294912   // fp16 weights: W2(65536) lw2(65536) W3(131072) lw3(32768)
#define MBLK   157      // ceil(20000/128)
#define GATBLK 2500     // ceil(20000/8)
#define HISTBLK 1250    // ceil(NEDGES/256)
#define SCATBLK 1329    // ceil(NEPLUS/256)
#define L1BLK   10000   // NNODES*128/256

// ---------------- scratch (device globals; no runtime alloc allowed) ----------------
__device__ float  g_feat [2][NNODES * 128];
__device__ __half g_feath[2][NNODES * 256];
__device__ __half g_xh   [2][NNODES * 512];
__device__ float  g_lin  [2][NNODES * 256];
__device__ float  g_asb  [3][2][NNODES * 4];
__device__ float  g_adb  [3][2][NNODES * 4];
__device__ int    g_off  [2][NNODES + 1];
__device__ int    g_cur  [2][NNODES];
__device__ int    g_srcs [2][NEPLUS];
__device__ int    g_gcnt [2][NGRAPH];
__device__ int    g_bsum [2][128];
__device__ float  g_tab  [VOCAB * 512];
__device__ float  g_tatt [VOCAB * 8];
__device__ __half g_wh   [NWH];

__device__ __forceinline__ float lrelu(float x) { return x > 0.f ? x : 0.2f * x; }

__device__ __forceinline__ uint32_t sptr(const void* p) {
    return (uint32_t)__cvta_generic_to_shared(p);
}
#define CPA(dst, src, sz) \
    asm volatile("cp.async.cg.shared.global [%0], [%1], 16, %2;" :: "r"(dst), "l"(src), "r"(sz))
#define CP_COMMIT() asm volatile("cp.async.commit_group;" ::: "memory")
#define CP_WAIT1()  asm volatile("cp.async.wait_group 1;" ::: "memory")
#define CP_WAIT0()  asm volatile("cp.async.wait_group 0;" ::: "memory")

// ---------------- init A (main stream): CSR counts, pool, out (both sides) ----------
__global__ void k_init_csr(float* out) {
    int i = blockIdx.x * blockDim.x + threadIdx.x;
    if (i < 2 * NNODES) g_cur[i / NNODES][i % NNODES] = 1;
    if (i < 2 * NGRAPH * 128) out[i] = 0.f;
    if (i < 2 * NGRAPH) g_gcnt[i >> 8][i & 255] = 0;
}

// ---------------- init B (side stream): weight fp16 conversion + score zero ---------
__global__ void k_wconv_zero(const float* __restrict__ W2, const float* __restrict__ lw2,
                             const float* __restrict__ W3, const float* __restrict__ lw3) {
    int i = blockIdx.x * blockDim.x + threadIdx.x;
    if (i < NWH) {
        float v;
        if (i < 65536)       v = W2[i];
        else if (i < 131072) v = lw2[i - 65536];
        else if (i < 262144) v = W3[i - 131072];
        else                 v = lw3[i - 262144];
        g_wh[i] = __float2half_rn(v);
    }
    if (i < 2 * 2 * NNODES * 4) {
        int l = 1 + i / (2 * NNODES * 4);
        int r = i % (2 * NNODES * 4);
        g_asb[l][r / (NNODES * 4)][r % (NNODES * 4)] = 0.f;
        g_adb[l][r / (NNODES * 4)][r % (NNODES * 4)] = 0.f;
    }
}

// ---------------- FUSED (main): vocab table precompute + side-L histogram -----------
__global__ void k_pre_hist(const float* __restrict__ emb, const float* __restrict__ W1,
                           const float* __restrict__ lw1, const float* __restrict__ as1,
                           const float* __restrict__ ad1, const int* __restrict__ el) {
    __shared__ float er_s[128];
    __shared__ float sAs[4], sAd[4];
    int t = threadIdx.x;
    if ((int)blockIdx.x < VOCAB) {
        int v = blockIdx.x;
        if (t < 128) er_s[t] = emb[v * 128 + t];
        if (t < 4) { sAs[t] = 0.f; sAd[t] = 0.f; }
        __syncthreads();
        float acc0 = 0.f, acc1 = 0.f;
        for (int k = 0; k < 128; k++) {
            float e = er_s[k];
            acc0 += e * W1[k * 256 + t];
            acc1 += e * lw1[k * 256 + t];
        }
        g_tab[v * 512 + t] = acc0;
        g_tab[v * 512 + 256 + t] = acc1;
        int h = t >> 6, c = t & 63;
        atomicAdd(&sAs[h], acc0 * as1[h * 64 + c]);
        atomicAdd(&sAd[h], acc0 * ad1[h * 64 + c]);
        __syncthreads();
        if (t < 4) { g_tatt[v * 8 + t] = sAs[t]; g_tatt[v * 8 + 4 + t] = sAd[t]; }
    } else {
        int e = (blockIdx.x - VOCAB) * 256 + t;
        if (e < NEDGES) atomicAdd(&g_cur[0][el[NEDGES + e]], 1);
    }
}

// ---------------- side-R histogram ----------------
__global__ void k_hist(int side, const int* __restrict__ edge) {
    int e = blockIdx.x * blockDim.x + threadIdx.x;
    if (e < NEDGES) atomicAdd(&g_cur[side][edge[NEDGES + e]], 1);
}

// ---------------- scan (per side) ----------------
__global__ void k_scan_a(int side) {
    __shared__ int sh[256];
    int t = threadIdx.x, i = blockIdx.x * 256 + t;
    int v = (i < NNODES) ? g_cur[side][i] : 0;
    sh[t] = v;
    __syncthreads();
    for (int o = 1; o < 256; o <<= 1) {
        int x = (t >= o) ? sh[t - o] : 0;
        __syncthreads();
        sh[t] += x;
        __syncthreads();
    }
    if (i < NNODES) g_off[side][i] = sh[t] - v;
    if (t == 255) g_bsum[side][blockIdx.x] = sh[255];
}
__global__ void k_scan_c(int side) {
    int bx = blockIdx.x, t = threadIdx.x;
    __shared__ int sbase;
    if (t < 32) {
        int s = 0;
        for (int j = t; j < 79; j += 32)
            if (j < bx) s += g_bsum[side][j];
        for (int o = 16; o; o >>= 1) s += __shfl_xor_sync(0xffffffffu, s, o);
        if (t == 0) sbase = s;
    }
    __syncthreads();
    int base = sbase;
    int i = bx * 256 + t;
    if (i < NNODES) {
        int o = g_off[side][i] + base;
        g_off[side][i] = o;
        g_cur[side][i] = o;
    }
    if (i == 0) g_off[side][NNODES] = NEPLUS;
}

// ---------------- FUSED (per side): edge scatter + layer-1 table gather -------------
__global__ void k_scat_l1(int side, const int* __restrict__ edge, const int* __restrict__ xi) {
    int t = threadIdx.x;
    if ((int)blockIdx.x < SCATBLK) {
        int e = blockIdx.x * 256 + t;
        if (e < NEPLUS) {
            int s, d;
            if (e < NEDGES) { s = edge[e]; d = edge[NEDGES + e]; }
            else            { s = d = e - NEDGES; }
            int p = atomicAdd(&g_cur[side][d], 1);
            g_srcs[side][p] = s;
        }
    } else {
        int idx = (blockIdx.x - SCATBLK) * 256 + t;
        int n = idx >> 7, q = idx & 127;
        int v = xi[n];
        float4 val = *(const float4*)(g_tab + v * 512 + q * 4);
        if (q < 64) {
            __half2 h0 = __floats2half2_rn(val.x, val.y);
            __half2 h1 = __floats2half2_rn(val.z, val.w);
            uint2 u = make_uint2(*(uint32_t*)&h0, *(uint32_t*)&h1);
            *(uint2*)(&g_xh[side][n * 256 + q * 4]) = u;
        } else {
            *(float4*)(&g_lin[side][n * 256 + (q - 64) * 4]) = val;
        }
        if (q == 0) {
            *(float4*)(&g_asb[0][side][n * 4]) = *(const float4*)(g_tatt + v * 8);
            *(float4*)(&g_adb[0][side][n * 4]) = *(const float4*)(g_tatt + v * 8 + 4);
        }
    }
}

// ---------------- fp16 GEMM with fused attention-score epilogue (per side) ----------
__device__ __forceinline__ void mma_f16(float* c, const unsigned* a, const unsigned* b) {
    asm volatile(
        "mma.sync.aligned.m16n8k16.row.col.f32.f16.f16.f32 "
        "{%0,%1,%2,%3},{%4,%5,%6,%7},{%8,%9},{%0,%1,%2,%3};"
        : "+f"(c[0]), "+f"(c[1]), "+f"(c[2]), "+f"(c[3])
        : "r"(a[0]), "r"(a[1]), "r"(a[2]), "r"(a[3]),
          "r"(b[0]), "r"(b[1]));
}

#define AS_STRIDE 40
#define BS_STRIDE 136
#define GEMM_SMEM ((2 * 128 * AS_STRIDE + 2 * 32 * BS_STRIDE) * 2)

__global__ __launch_bounds__(256) void k_gemm(
    int side, int layer,
    const __half* __restrict__ B1, int N1,
    const __half* __restrict__ B2, int N2,
    int K, const float* __restrict__ atts, const float* __restrict__ attd, int C) {
    extern __shared__ __half smh[];
    __half (*As)[128][AS_STRIDE] = (__half (*)[128][AS_STRIDE])smh;
    __half (*Bs)[32][BS_STRIDE] = (__half (*)[32][BS_STRIDE])(smh + 2 * 128 * AS_STRIDE);

    int bx = blockIdx.x, by = blockIdx.y;
    const int M = NNODES;
    const __half* A = g_feath[side];
    int t1 = N1 >> 7;
    bool ishalf = (bx < t1);
    const __half* B; int N, n0;
    __half* Ch = g_xh[side];
    float* Cf = g_lin[side];
    if (ishalf) { B = B1; N = N1; n0 = bx << 7; }
    else        { B = B2; N = N2; n0 = (bx - t1) << 7; }

    int tid = threadIdx.x;
    int warp = tid >> 5, lane = tid & 31;
    int m0 = by * 128;
    int wm = (warp >> 2) * 64;
    int wn = (warp & 3) * 32;
    int gid = lane >> 2, tig = lane & 3;

    float c[4][4][4];
#pragma unroll
    for (int i = 0; i < 4; i++)
#pragma unroll
        for (int j = 0; j < 4; j++)
#pragma unroll
            for (int r = 0; r < 4; r++) c[i][j][r] = 0.f;

    auto load_tile = [&](int s, int kk) {
#pragma unroll
        for (int i = 0; i < 2; i++) {
            int cid = tid + 256 * i;
            int row = cid >> 2, coff = (cid & 3) * 8;
            const __half* asrc = A + (size_t)(m0 + row) * K + kk + coff;
            int sz = (m0 + row < M) ? 16 : 0;
            if (!sz) asrc = A;
            CPA(sptr(&As[s][row][coff]), asrc, sz);
            int krow = cid >> 4, noff = (cid & 15) * 8;
            const __half* bsrc = B + (size_t)(kk + krow) * N + n0 + noff;
            CPA(sptr(&Bs[s][krow][noff]), bsrc, 16);
        }
        CP_COMMIT();
    };

    auto compute = [&](int s) {
#pragma unroll
        for (int ks = 0; ks < 2; ks++) {
            unsigned a[4][4], b[4][2];
#pragma unroll
            for (int mi = 0; mi < 4; mi++) {
                uint32_t addr = sptr(&As[s][wm + mi * 16 + (lane & 15)][ks * 16 + (lane >> 4) * 8]);
                asm volatile("ldmatrix.sync.aligned.m8n8.x4.shared.b16 {%0,%1,%2,%3}, [%4];"
                             : "=r"(a[mi][0]), "=r"(a[mi][1]), "=r"(a[mi][2]), "=r"(a[mi][3])
                             : "r"(addr));
            }
#pragma unroll
            for (int ni = 0; ni < 4; ni++) {
                uint32_t addr = sptr(&Bs[s][ks * 16 + (lane & 15)][wn + ni * 8]);
                asm volatile("ldmatrix.sync.aligned.m8n8.x2.trans.shared.b16 {%0,%1}, [%2];"
                             : "=r"(b[ni][0]), "=r"(b[ni][1])
                             : "r"(addr));
            }
#pragma unroll
            for (int mi = 0; mi < 4; mi++)
#pragma unroll
                for (int ni = 0; ni < 4; ni++) mma_f16(c[mi][ni], a[mi], b[ni]);
        }
    };

    int KT = K >> 5;
    load_tile(0, 0);
    for (int kt = 0; kt < KT; kt++) {
        if (kt + 1 < KT) {
            load_tile((kt + 1) & 1, (kt + 1) << 5);
            CP_WAIT1();
        } else {
            CP_WAIT0();
        }
        __syncthreads();
        compute(kt & 1);
        __syncthreads();
    }
#pragma unroll
    for (int mi = 0; mi < 4; mi++) {
#pragma unroll
        for (int ni = 0; ni < 4; ni++) {
            int r0 = m0 + wm + mi * 16 + gid;
            int cc = n0 + wn + ni * 8 + tig * 2;
            if (ishalf) {
                if (r0 < M)
                    *(__half2*)(Ch + (size_t)r0 * N + cc) =
                        __floats2half2_rn(c[mi][ni][0], c[mi][ni][1]);
                if (r0 + 8 < M)
                    *(__half2*)(Ch + (size_t)(r0 + 8) * N + cc) =
                        __floats2half2_rn(c[mi][ni][2], c[mi][ni][3]);
            } else {
                if (r0 < M)
                    *(float2*)(Cf + (size_t)r0 * N + cc) = make_float2(c[mi][ni][0], c[mi][ni][1]);
                if (r0 + 8 < M)
                    *(float2*)(Cf + (size_t)(r0 + 8) * N + cc) = make_float2(c[mi][ni][2], c[mi][ni][3]);
            }
        }
    }
    if (ishalf) {
        int h = (n0 + wn) / C;
        float av0[4], av1[4], bv0[4], bv1[4];
#pragma unroll
        for (int ni = 0; ni < 4; ni++) {
            int cc = n0 + wn + ni * 8 + tig * 2;
            av0[ni] = atts[cc]; av1[ni] = atts[cc + 1];
            bv0[ni] = attd[cc]; bv1[ni] = attd[cc + 1];
        }
        float* asb = g_asb[layer][side];
        float* adb = g_adb[layer][side];
#pragma unroll
        for (int mi = 0; mi < 4; mi++) {
            float s0 = 0.f, s1 = 0.f, d0 = 0.f, d1 = 0.f;
#pragma unroll
            for (int ni = 0; ni < 4; ni++) {
                s0 += c[mi][ni][0] * av0[ni] + c[mi][ni][1] * av1[ni];
                s1 += c[mi][ni][2] * av0[ni] + c[mi][ni][3] * av1[ni];
                d0 += c[mi][ni][0] * bv0[ni] + c[mi][ni][1] * bv1[ni];
                d1 += c[mi][ni][2] * bv0[ni] + c[mi][ni][3] * bv1[ni];
            }
#pragma unroll
            for (int o = 1; o <= 2; o <<= 1) {
                s0 += __shfl_xor_sync(0xffffffffu, s0, o);
                s1 += __shfl_xor_sync(0xffffffffu, s1, o);
                d0 += __shfl_xor_sync(0xffffffffu, d0, o);
                d1 += __shfl_xor_sync(0xffffffffu, d1, o);
            }
            if (tig == 0) {
                int r0 = m0 + wm + mi * 16 + gid;
                if (r0 < M) {
                    atomicAdd(&asb[r0 * 4 + h], s0);
                    atomicAdd(&adb[r0 * 4 + h], d0);
                }
                if (r0 + 8 < M) {
                    atomicAdd(&asb[(r0 + 8) * 4 + h], s1);
                    atomicAdd(&adb[(r0 + 8) * 4 + h], d1);
                }
            }
        }
    }
}

// ---------------- GAT kernels: pass A computes z; pass B recomputes w ----------
__global__ __launch_bounds__(256) void k_gat_concat(
    int side, int layer, const float* __restrict__ bias, const float* __restrict__ lbias,
    int relu_flag) {
    int i = blockIdx.x * 8 + (threadIdx.x >> 5);
    int lane = threadIdx.x & 31;
    if (i >= NNODES) return;
    int beg = g_off[side][i], end = g_off[side][i + 1];
    const float* asbuf = g_asb[layer][side];
    float4 ad = *(const float4*)(&g_adb[layer][side][(size_t)i * 4]);
    float z0 = 0.f, z1 = 0.f, z2 = 0.f, z3 = 0.f;
    for (int e = beg + lane; e < end; e += 32) {
        int s = g_srcs[side][e];
        float4 as = *(const float4*)(&asbuf[(size_t)s * 4]);
        z0 += __expf(fminf(lrelu(as.x + ad.x), 80.f));
        z1 += __expf(fminf(lrelu(as.y + ad.y), 80.f));
        z2 += __expf(fminf(lrelu(as.z + ad.z), 80.f));
        z3 += __expf(fminf(lrelu(as.w + ad.w), 80.f));
    }
    for (int o = 16; o; o >>= 1) {
        z0 += __shfl_xor_sync(0xffffffffu, z0, o);
        z1 += __shfl_xor_sync(0xffffffffu, z1, o);
        z2 += __shfl_xor_sync(0xffffffffu, z2, o);
        z3 += __shfl_xor_sync(0xffffffffu, z3, o);
    }
    float i0 = 1.f / (z0 + 1e-16f), i1 = 1.f / (z1 + 1e-16f);
    float i2 = 1.f / (z2 + 1e-16f), i3 = 1.f / (z3 + 1e-16f);
    int h = lane >> 3;
    float myinv = (h == 0) ? i0 : (h == 1) ? i1 : (h == 2) ? i2 : i3;
    float adh = (h == 0) ? ad.x : (h == 1) ? ad.y : (h == 2) ? ad.z : ad.w;
    int col = lane * 8;
    float a0 = 0.f, a1 = 0.f, a2 = 0.f, a3 = 0.f, a4 = 0.f, a5 = 0.f, a6 = 0.f, a7 = 0.f;
    for (int e = beg; e < end; e++) {
        int s = g_srcs[side][e];
        float ash = asbuf[(size_t)s * 4 + h];
        float w = __expf(fminf(lrelu(ash + adh), 80.f)) * myinv;
        uint4 u = *(const uint4*)(g_xh[side] + (size_t)s * 256 + col);
        __half2* hp = (__half2*)&u;
        float2 f0 = __half22float2(hp[0]);
        float2 f1 = __half22float2(hp[1]);
        float2 f2 = __half22float2(hp[2]);
        float2 f3 = __half22float2(hp[3]);
        a0 += w * f0.x; a1 += w * f0.y; a2 += w * f1.x; a3 += w * f1.y;
        a4 += w * f2.x; a5 += w * f2.y; a6 += w * f3.x; a7 += w * f3.y;
    }
    float4 lr0 = *(const float4*)(g_lin[side] + (size_t)i * 256 + col);
    float4 lr1 = *(const float4*)(g_lin[side] + (size_t)i * 256 + col + 4);
    float4 b0 = *(const float4*)(bias + col);
    float4 b1 = *(const float4*)(bias + col + 4);
    float4 lb0 = *(const float4*)(lbias + col);
    float4 lb1 = *(const float4*)(lbias + col + 4);
    float o0x = a0 + b0.x + lr0.x + lb0.x, o0y = a1 + b0.y + lr0.y + lb0.y;
    float o0z = a2 + b0.z + lr0.z + lb0.z, o0w = a3 + b0.w + lr0.w + lb0.w;
    float o1x = a4 + b1.x + lr1.x + lb1.x, o1y = a5 + b1.y + lr1.y + lb1.y;
    float o1z = a6 + b1.z + lr1.z + lb1.z, o1w = a7 + b1.w + lr1.w + lb1.w;
    if (relu_flag) {
        o0x = fmaxf(o0x, 0.f); o0y = fmaxf(o0y, 0.f);
        o0z = fmaxf(o0z, 0.f); o0w = fmaxf(o0w, 0.f);
        o1x = fmaxf(o1x, 0.f); o1y = fmaxf(o1y, 0.f);
        o1z = fmaxf(o1z, 0.f); o1w = fmaxf(o1w, 0.f);
    }
    __half2 h0 = __floats2half2_rn(o0x, o0y);
    __half2 h1 = __floats2half2_rn(o0z, o0w);
    __half2 h2 = __floats2half2_rn(o1x, o1y);
    __half2 h3 = __floats2half2_rn(o1z, o1w);
    uint4 uo = make_uint4(*(uint32_t*)&h0, *(uint32_t*)&h1, *(uint32_t*)&h2, *(uint32_t*)&h3);
    *(uint4*)(&g_feath[side][(size_t)i * 256 + col]) = uo;
}

__global__ __launch_bounds__(256) void k_gat_mean(
    int side, const float* __restrict__ bias, const float* __restrict__ lbias) {
    int i = blockIdx.x * 8 + (threadIdx.x >> 5);
    int lane = threadIdx.x & 31;
    if (i >= NNODES) return;
    int beg = g_off[side][i], end = g_off[side][i + 1];
    const float* asbuf = g_asb[2][side];
    float4 ad = *(const float4*)(&g_adb[2][side][(size_t)i * 4]);
    float z0 = 0.f, z1 = 0.f, z2 = 0.f, z3 = 0.f;
    for (int e = beg + lane; e < end; e += 32) {
        int s = g_srcs[side][e];
        float4 as = *(const float4*)(&asbuf[(size_t)s * 4]);
        z0 += __expf(fminf(lrelu(as.x + ad.x), 80.f));
        z1 += __expf(fminf(lrelu(as.y + ad.y), 80.f));
        z2 += __expf(fminf(lrelu(as.z + ad.z), 80.f));
        z3 += __expf(fminf(lrelu(as.w + ad.w), 80.f));
    }
    for (int o = 16; o; o >>= 1) {
        z0 += __shfl_xor_sync(0xffffffffu, z0, o);
        z1 += __shfl_xor_sync(0xffffffffu, z1, o);
        z2 += __shfl_xor_sync(0xffffffffu, z2, o);
        z3 += __shfl_xor_sync(0xffffffffu, z3, o);
    }
    float i0 = 1.f / (z0 + 1e-16f), i1 = 1.f / (z1 + 1e-16f);
    float i2 = 1.f / (z2 + 1e-16f), i3 = 1.f / (z3 + 1e-16f);
    int h = lane >> 3;
    float myinv = (h == 0) ? i0 : (h == 1) ? i1 : (h == 2) ? i2 : i3;
    float adh = (h == 0) ? ad.x : (h == 1) ? ad.y : (h == 2) ? ad.z : ad.w;
    int col = lane * 16;
    float acc[16];
#pragma unroll
    for (int j = 0; j < 16; j++) acc[j] = 0.f;
    for (int e = beg; e < end; e++) {
        int s = g_srcs[side][e];
        float ash = asbuf[(size_t)s * 4 + h];
        float w = __expf(fminf(lrelu(ash + adh), 80.f)) * myinv;
        const uint4* xr = (const uint4*)(g_xh[side] + (size_t)s * 512 + col);
        uint4 u0 = xr[0], u1 = xr[1];
        __half2* hp0 = (__half2*)&u0;
        __half2* hp1 = (__half2*)&u1;
#pragma unroll
        for (int j = 0; j < 4; j++) {
            float2 f = __half22float2(hp0[j]);
            acc[j * 2] += w * f.x; acc[j * 2 + 1] += w * f.y;
        }
#pragma unroll
        for (int j = 0; j < 4; j++) {
            float2 f = __half22float2(hp1[j]);
            acc[8 + j * 2] += w * f.x; acc[8 + j * 2 + 1] += w * f.y;
        }
    }
#pragma unroll
    for (int mask = 8; mask <= 16; mask <<= 1)
#pragma unroll
        for (int j = 0; j < 16; j++)
            acc[j] += __shfl_xor_sync(0xffffffffu, acc[j], mask);
    if (lane < 8) {
        int c0 = lane * 16;
#pragma unroll
        for (int j = 0; j < 4; j++) {
            int c = c0 + j * 4;
            float4 lr = *(const float4*)(g_lin[side] + (size_t)i * 128 + c);
            float4 bb = *(const float4*)(bias + c);
            float4 lb = *(const float4*)(lbias + c);
            float4 o;
            o.x = 0.25f * acc[j * 4 + 0] + bb.x + lr.x + lb.x;
            o.y = 0.25f * acc[j * 4 + 1] + bb.y + lr.y + lb.y;
            o.z = 0.25f * acc[j * 4 + 2] + bb.z + lr.z + lb.z;
            o.w = 0.25f * acc[j * 4 + 3] + bb.w + lr.w + lb.w;
            *(float4*)(g_feat[side] + (size_t)i * 128 + c) = o;
        }
    }
}

// ---------------- global mean pool ----------------
#define POOL_NB 64
__global__ void k_pool_sum(int side, const int* __restrict__ batch, float* out) {
    float* po = out + side * NGRAPH * 128;
    int n0 = blockIdx.x * POOL_NB;
    int c = threadIdx.x & 127;
    int r = threadIdx.x >> 7;
    float acc = 0.f;
    int cur = -1, cnt = 0;
    for (int j = r; j < POOL_NB; j += 2) {
        int n = n0 + j;
        if (n >= NNODES) break;
        int b = batch[n];
        if (b != cur) {
            if (cur >= 0) {
                atomicAdd(&po[cur * 128 + c], acc);
                if (c == 0) atomicAdd(&g_gcnt[side][cur], cnt);
            }
            acc = 0.f; cnt = 0; cur = b;
        }
        acc += g_feat[side][(size_t)n * 128 + c];
        cnt++;
    }
    if (cur >= 0) {
        atomicAdd(&po[cur * 128 + c], acc);
        if (c == 0) atomicAdd(&g_gcnt[side][cur], cnt);
    }
}
__global__ void k_pool_div(float* out) {
    int i = blockIdx.x * blockDim.x + threadIdx.x;
    if (i < 2 * NGRAPH * 128) {
        int side = i >> 15;
        float cnt = (float)g_gcnt[side][(i >> 7) & 255];
        out[i] /= fmaxf(cnt, 1.f);
    }
}

// ---------------- host orchestration: fully per-side pipelines ----------------
extern "C" void kernel_launch(void* const* d_in, const int* in_sizes, int n_in,
                              void* d_out, int out_size) {
    const int* x_l     = (const int*)d_in[0];
    const int* edge_l  = (const int*)d_in[1];
    const int* batch_l = (const int*)d_in[2];
    const int* x_r     = (const int*)d_in[3];
    const int* edge_r  = (const int*)d_in[4];
    const int* batch_r = (const int*)d_in[5];
    const float* emb = (const float*)d_in[6];
    const float* W1  = (const float*)d_in[7];  const float* as1 = (const float*)d_in[8];
    const float* ad1 = (const float*)d_in[9];  const float* b1  = (const float*)d_in[10];
    const float* lw1 = (const float*)d_in[11]; const float* lb1 = (const float*)d_in[12];
    const float* W2  = (const float*)d_in[13]; const float* as2 = (const float*)d_in[14];
    const float* ad2 = (const float*)d_in[15]; const float* b2  = (const float*)d_in[16];
    const float* lw2 = (const float*)d_in[17]; const float* lb2 = (const float*)d_in[18];
    const float* W3  = (const float*)d_in[19]; const float* as3 = (const float*)d_in[20];
    const float* ad3 = (const float*)d_in[21]; const float* b3  = (const float*)d_in[22];
    const float* lw3 = (const float*)d_in[23]; const float* lb3 = (const float*)d_in[24];
    float* out = (float*)d_out;

    __half* wh;
    cudaGetSymbolAddress((void**)&wh, g_wh);

    cudaFuncSetAttribute(k_gemm, cudaFuncAttributeMaxDynamicSharedMemorySize, GEMM_SMEM);

    const int TB = 256;
    int wz_grid = (2 * 2 * NNODES * 4 + TB - 1) / TB;
    if ((NWH + TB - 1) / TB > wz_grid) wz_grid = (NWH + TB - 1) / TB;

    // fork machinery (created per call; not destroyed — kernel_launch runs twice on host)
    cudaStream_t s1;
    cudaStreamCreateWithFlags(&s1, cudaStreamNonBlocking);
    cudaEvent_t evInit, evPre, evW, evJoin;
    cudaEventCreateWithFlags(&evInit, cudaEventDisableTiming);
    cudaEventCreateWithFlags(&evPre, cudaEventDisableTiming);
    cudaEventCreateWithFlags(&evW, cudaEventDisableTiming);
    cudaEventCreateWithFlags(&evJoin, cudaEventDisableTiming);

    const __half *W2h = wh, *lw2h = wh + 65536, *W3h = wh + 131072, *lw3h = wh + 262144;
    dim3 gemm2(4, MBLK), gemm3(5, MBLK);

    // main: shared init (both sides' counters)
    k_init_csr<<<(2 * NGRAPH * 128 + TB - 1) / TB, TB>>>(out);
    cudaEventRecord(evInit, 0);

    // s1 prologue: weights + score zeroing, then side-R CSR (stagger arises naturally)
    cudaStreamWaitEvent(s1, evInit, 0);
    k_wconv_zero<<<wz_grid, TB, 0, s1>>>(W2, lw2, W3, lw3);
    cudaEventRecord(evW, s1);
    k_hist<<<HISTBLK, TB, 0, s1>>>(1, edge_r);
    k_scan_a<<<79, 256, 0, s1>>>(1);
    k_scan_c<<<79, 256, 0, s1>>>(1);

    // main prologue: vocab table + side-L CSR
    k_pre_hist<<<VOCAB + HISTBLK, TB>>>(emb, W1, lw1, as1, ad1, edge_l);
    cudaEventRecord(evPre, 0);
    k_scan_a<<<79, 256>>>(0);
    k_scan_c<<<79, 256>>>(0);
    k_scat_l1<<<SCATBLK + L1BLK, TB>>>(0, edge_l, x_l);

    // side L layers (main)
    k_gat_concat<<<GATBLK, TB>>>(0, 0, b1, lb1, 1);
    cudaStreamWaitEvent(0, evW, 0);
    k_gemm<<<gemm2, 256, GEMM_SMEM>>>(0, 1, W2h, 256, lw2h, 256, 256, as2, ad2, 64);
    k_gat_concat<<<GATBLK, TB>>>(0, 1, b2, lb2, 1);
    k_gemm<<<gemm3, 256, GEMM_SMEM>>>(0, 2, W3h, 512, lw3h, 128, 256, as3, ad3, 128);
    k_gat_mean<<<GATBLK, TB>>>(0, b3, lb3);
    k_pool_sum<<<(NNODES + POOL_NB - 1) / POOL_NB, TB>>>(0, batch_l, out);

    // side R layers (s1); scat needs the vocab table from main
    cudaStreamWaitEvent(s1, evPre, 0);
    k_scat_l1<<<SCATBLK + L1BLK, TB, 0, s1>>>(1, edge_r, x_r);
    k_gat_concat<<<GATBLK, TB, 0, s1>>>(1, 0, b1, lb1, 1);
    k_gemm<<<gemm2, 256, GEMM_SMEM, s1>>>(1, 1, W2h, 256, lw2h, 256, 256, as2, ad2, 64);
    k_gat_concat<<<GATBLK, TB, 0, s1>>>(1, 1, b2, lb2, 1);
    k_gemm<<<gemm3, 256, GEMM_SMEM, s1>>>(1, 2, W3h, 512, lw3h, 128, 256, as3, ad3, 128);
    k_gat_mean<<<GATBLK, TB, 0, s1>>>(1, b3, lb3);
    k_pool_sum<<<(NNODES + POOL_NB - 1) / POOL_NB, TB, 0, s1>>>(1, batch_r, out);
    cudaEventRecord(evJoin, s1);

    // rejoin and finish
    cudaStreamWaitEvent(0, evJoin, 0);
    k_pool_div<<<(2 * NGRAPH * 128 + TB - 1) / TB, TB>>>(out);
}